// round 3
// baseline (speedup 1.0000x reference)
#include <cuda_runtime.h>
#include <cuda_bf16.h>
#include <math.h>

#define NN 50000
#define CC 256
#define HH 4
#define DD 64
#define EE 800000
#define OC 256   // H*D

// ---------------- device scratch (static globals: allowed) ----------------
__device__ float g_q[NN * CC];
__device__ float g_k[NN * CC];
__device__ float g_v[NN * CC];
__device__ float g_vbar[NN * DD];
__device__ float g_ksum[OC];
__device__ float g_vsum[OC];
__device__ float g_kv[HH * DD * DD];
__device__ float g_scal[2];          // sumsq(q), sumsq(k)
__device__ float g_deg[NN];
__device__ int   g_offs[NN + 1];
__device__ int   g_cursor[NN];
__device__ int   g_src[EE];
__device__ float g_val[EE];

// ---------------- 0: zero scratch ----------------
__global__ void zero_kernel() {
    int i = blockIdx.x * 256 + threadIdx.x;
    if (i < NN) g_deg[i] = 0.f;
    if (i < HH * DD * DD) g_kv[i] = 0.f;
    if (i < OC) { g_ksum[i] = 0.f; g_vsum[i] = 0.f; }
    if (i < 2) g_scal[i] = 0.f;
}

// ---------------- 1: fused QKV GEMM, O = X @ W^T + b ----------------
// block 256 threads computes a 128x128 tile, 8x8 per thread, K-steps of 8.
__global__ void gemm_qkv(const float* __restrict__ Xq, const float* __restrict__ Xs,
                         const float* __restrict__ Wq, const float* __restrict__ bq,
                         const float* __restrict__ Wk, const float* __restrict__ bk,
                         const float* __restrict__ Wv, const float* __restrict__ bv)
{
    __shared__ float As[8][128];
    __shared__ float Bs[8][128];
    int t  = threadIdx.x;
    int bm = blockIdx.y;          // 0..390
    int bn = blockIdx.x;          // 0..5
    int which = bn >> 1;          // 0=q 1=k 2=v
    const float* X = (which == 0) ? Xq : Xs;
    const float* W = (which == 0) ? Wq : (which == 1 ? Wk : Wv);
    const float* B = (which == 0) ? bq : (which == 1 ? bk : bv);
    float* O = (which == 0) ? g_q : (which == 1 ? g_k : g_v);
    int n0 = (bn & 1) * 128;
    int m0 = bm * 128;

    int lr = t >> 1;              // 0..127
    int lk = (t & 1) * 4;         // 0 or 4
    int ty = t >> 4, tx = t & 15;

    float acc[8][8];
#pragma unroll
    for (int i = 0; i < 8; i++)
#pragma unroll
        for (int j = 0; j < 8; j++) acc[i][j] = 0.f;

    for (int k0 = 0; k0 < CC; k0 += 8) {
        int row = m0 + lr;
        float4 av = make_float4(0.f, 0.f, 0.f, 0.f);
        if (row < NN) av = *(const float4*)&X[(size_t)row * CC + k0 + lk];
        As[lk + 0][lr] = av.x; As[lk + 1][lr] = av.y;
        As[lk + 2][lr] = av.z; As[lk + 3][lr] = av.w;
        float4 wv = *(const float4*)&W[(size_t)(n0 + lr) * CC + k0 + lk];
        Bs[lk + 0][lr] = wv.x; Bs[lk + 1][lr] = wv.y;
        Bs[lk + 2][lr] = wv.z; Bs[lk + 3][lr] = wv.w;
        __syncthreads();
#pragma unroll
        for (int kk = 0; kk < 8; kk++) {
            float4 a0 = *(float4*)&As[kk][ty * 8];
            float4 a1 = *(float4*)&As[kk][ty * 8 + 4];
            float4 b0 = *(float4*)&Bs[kk][tx * 8];
            float4 b1 = *(float4*)&Bs[kk][tx * 8 + 4];
            float a[8] = {a0.x, a0.y, a0.z, a0.w, a1.x, a1.y, a1.z, a1.w};
            float b[8] = {b0.x, b0.y, b0.z, b0.w, b1.x, b1.y, b1.z, b1.w};
#pragma unroll
            for (int i = 0; i < 8; i++)
#pragma unroll
                for (int j = 0; j < 8; j++) acc[i][j] += a[i] * b[j];
        }
        __syncthreads();
    }

#pragma unroll
    for (int i = 0; i < 8; i++) {
        int row = m0 + ty * 8 + i;
        if (row < NN) {
            int c0 = n0 + tx * 8;
            float4 o0, o1;
            o0.x = acc[i][0] + B[c0 + 0]; o0.y = acc[i][1] + B[c0 + 1];
            o0.z = acc[i][2] + B[c0 + 2]; o0.w = acc[i][3] + B[c0 + 3];
            o1.x = acc[i][4] + B[c0 + 4]; o1.y = acc[i][5] + B[c0 + 5];
            o1.z = acc[i][6] + B[c0 + 6]; o1.w = acc[i][7] + B[c0 + 7];
            *(float4*)&O[(size_t)row * OC + c0]     = o0;
            *(float4*)&O[(size_t)row * OC + c0 + 4] = o1;
        }
    }
}

// ---------------- 2: row reductions: sumsq(q), sumsq(k), ksum, vsum, vbar ----------------
__global__ void reduce_rows() {
    int b = blockIdx.x;      // 196
    int c = threadIdx.x;     // 256
    __shared__ float sv[256];
    __shared__ float red[256];
    float qsq = 0.f, ksq = 0.f, ksa = 0.f, vsa = 0.f;
    int n0 = b * 256;
    int n1 = n0 + 256; if (n1 > NN) n1 = NN;
    for (int n = n0; n < n1; ++n) {
        float qv = g_q[(size_t)n * OC + c];
        float kv = g_k[(size_t)n * OC + c];
        float vv = g_v[(size_t)n * OC + c];
        qsq += qv * qv; ksq += kv * kv; ksa += kv; vsa += vv;
        sv[c] = vv;
        __syncthreads();
        if (c < 64)
            g_vbar[(size_t)n * 64 + c] =
                0.25f * (sv[c] + sv[c + 64] + sv[c + 128] + sv[c + 192]);
        __syncthreads();
    }
    atomicAdd(&g_ksum[c], ksa);
    atomicAdd(&g_vsum[c], vsa);
    red[c] = qsq; __syncthreads();
    for (int s = 128; s > 0; s >>= 1) { if (c < s) red[c] += red[c + s]; __syncthreads(); }
    if (c == 0) atomicAdd(&g_scal[0], red[0]);
    __syncthreads();
    red[c] = ksq; __syncthreads();
    for (int s = 128; s > 0; s >>= 1) { if (c < s) red[c] += red[c + s]; __syncthreads(); }
    if (c == 0) atomicAdd(&g_scal[1], red[0]);
}

// ---------------- 3: kv[h][m][d] = sum_n k[n,h,m]*v[n,h,d] ----------------
__global__ void kv_kernel() {
    int h = blockIdx.y;        // 0..3
    int chunk = blockIdx.x;    // 0..97
    __shared__ float sk[32][64];
    __shared__ float sw[32][64];
    int t = threadIdx.x;
    int m = t >> 2;            // 0..63
    int dg = t & 3;            // 0..3
    float acc[16];
#pragma unroll
    for (int j = 0; j < 16; j++) acc[j] = 0.f;
    int base = chunk * 512;
    for (int cs = 0; cs < 512; cs += 32) {
#pragma unroll
        for (int i = 0; i < 16; i++) {
            int idx = t + i * 256;   // 0..4095
            int r = idx >> 7;
            int col = idx & 127;
            int n = base + cs + r;
            float x = 0.f;
            if (n < NN) {
                if (col < 64) x = g_k[(size_t)n * OC + h * 64 + col];
                else          x = g_v[(size_t)n * OC + h * 64 + (col - 64)];
            }
            if (col < 64) sk[r][col] = x; else sw[r][col - 64] = x;
        }
        __syncthreads();
#pragma unroll
        for (int r = 0; r < 32; r++) {
            float km = sk[r][m];
#pragma unroll
            for (int j = 0; j < 16; j++) acc[j] += km * sw[r][dg * 16 + j];
        }
        __syncthreads();
    }
#pragma unroll
    for (int j = 0; j < 16; j++)
        atomicAdd(&g_kv[h * 4096 + m * 64 + dg * 16 + j], acc[j]);
}

// ---------------- 4: degree on col ----------------
__global__ void degree_kernel(const int* __restrict__ ei) {
    int e = blockIdx.x * 256 + threadIdx.x;
    if (e < EE) atomicAdd(&g_deg[ei[EE + e]], 1.0f);
}

// ---------------- 5: exclusive scan of degrees (single block) ----------------
__global__ void scan_kernel() {
    __shared__ int s[1024];
    int tid = threadIdx.x;
    int carry = 0;
    const int NCH = (NN + 1023) / 1024;
    for (int ch = 0; ch < NCH; ch++) {
        int i = ch * 1024 + tid;
        int x = (i < NN) ? (int)g_deg[i] : 0;
        s[tid] = x;
        __syncthreads();
        for (int off = 1; off < 1024; off <<= 1) {
            int tpl = 0;
            if (tid >= off) tpl = s[tid - off];
            __syncthreads();
            s[tid] += tpl;
            __syncthreads();
        }
        int incl = s[tid];
        int total = s[1023];
        if (i < NN) {
            int excl = carry + incl - x;
            g_offs[i] = excl;
            g_cursor[i] = excl;
        }
        carry += total;
        __syncthreads();
    }
    if (tid == 0) g_offs[NN] = carry;
}

// ---------------- 6: scatter edges into CSR-by-destination ----------------
__global__ void scatter_kernel(const int* __restrict__ ei, const float* __restrict__ ew) {
    int e = blockIdx.x * 256 + threadIdx.x;
    if (e >= EE) return;
    int r = ei[e];
    int c = ei[EE + e];
    float dc = g_deg[c];
    float dr = g_deg[r];
    float w = ew[e];
    float val = (dr > 0.f) ? w * rsqrtf(dc * dr) : 0.f;
    int slot = atomicAdd(&g_cursor[c], 1);
    g_src[slot] = r;
    g_val[slot] = val;
}

// ---------------- 7: attention epilogue ----------------
// dynamic smem: kvs tensor (4*64*64 floats = 64KB)
__global__ void attn_kernel(float* __restrict__ out) {
    extern __shared__ float skv[];     // 16384 floats
    __shared__ float sks[OC];
    __shared__ float svs[OC];
    __shared__ float sq[4][OC];
    int t = threadIdx.x;
    for (int i = t; i < HH * DD * DD; i += 256) skv[i] = g_kv[i];
    sks[t] = g_ksum[t];
    svs[t] = g_vsum[t];
    float scal = rsqrtf(g_scal[0]) * rsqrtf(g_scal[1]);  // 1/(||q||_F * ||k||_F)
    __syncthreads();
    int g = t >> 6, d = t & 63;
    int ngroups = (NN + 3) / 4;
    for (int grp = blockIdx.x; grp < ngroups; grp += gridDim.x) {
        int n = grp * 4 + g;
        if (n < NN) {
#pragma unroll
            for (int j = 0; j < 4; j++)
                sq[g][d + j * 64] = g_q[(size_t)n * OC + d + j * 64];
        }
        __syncthreads();
        if (n < NN) {
            float acc = 0.f;
#pragma unroll
            for (int h = 0; h < HH; h++) {
                float num = 0.f, den = 0.f;
                const float* kvp = &skv[h * 4096];
#pragma unroll
                for (int m = 0; m < 64; m++) {
                    float qm = sq[g][h * 64 + m];
                    num += qm * kvp[m * 64 + d];
                    den += qm * sks[h * 64 + m];
                }
                acc += (scal * num + svs[h * 64 + d]) / (scal * den + (float)NN);
            }
            out[(size_t)n * 64 + d] = 0.25f * acc;
        }
        __syncthreads();
    }
}

// ---------------- 8: GCN gather (atomic-free), out += sum ----------------
__global__ void gather_kernel(float* __restrict__ out) {
    int t = threadIdx.x;
    int n = blockIdx.x * 4 + (t >> 6);
    int d = t & 63;
    if (n >= NN) return;
    int e0 = g_offs[n], e1 = g_offs[n + 1];
    float acc = 0.f;
    for (int e = e0; e < e1; ++e) {
        int r = g_src[e];
        float val = g_val[e];
        acc += val * g_vbar[(size_t)r * 64 + d];
    }
    out[(size_t)n * 64 + d] += acc;
}

// ---------------- launch ----------------
extern "C" void kernel_launch(void* const* d_in, const int* in_sizes, int n_in,
                              void* d_out, int out_size) {
    const float* query = (const float*)d_in[0];
    const float* source = (const float*)d_in[1];
    const float* Wq = (const float*)d_in[2];
    const float* bq = (const float*)d_in[3];
    const float* Wk = (const float*)d_in[4];
    const float* bk = (const float*)d_in[5];
    const float* Wv = (const float*)d_in[6];
    const float* bv = (const float*)d_in[7];
    const int*   ei = (const int*)d_in[8];
    const float* ew = (const float*)d_in[9];
    float* out = (float*)d_out;

    cudaFuncSetAttribute(attn_kernel, cudaFuncAttributeMaxDynamicSharedMemorySize,
                         HH * DD * DD * (int)sizeof(float));

    zero_kernel<<<196, 256>>>();
    gemm_qkv<<<dim3(6, 391), 256>>>(query, source, Wq, bq, Wk, bk, Wv, bv);
    reduce_rows<<<196, 256>>>();
    kv_kernel<<<dim3(98, 4), 256>>>();
    degree_kernel<<<(EE + 255) / 256, 256>>>(ei);
    scan_kernel<<<1, 1024>>>();
    scatter_kernel<<<(EE + 255) / 256, 256>>>(ei, ew);
    attn_kernel<<<444, 256, HH * DD * DD * sizeof(float)>>>(out);
    gather_kernel<<<(NN + 3) / 4, 256>>>(out);
}

// round 5
// speedup vs baseline: 3.5123x; 3.5123x over previous
#include <cuda_runtime.h>
#include <cuda_bf16.h>
#include <math.h>
#include <stdint.h>

#define NN 50000
#define CC 256
#define HH 4
#define DD 64
#define EE 800000
#define OC 256   // H*D

// ---------------- device scratch ----------------
__device__ float g_q[NN * CC];
__device__ float g_k[NN * CC];
__device__ float g_v[NN * CC];
__device__ float g_vbar[NN * DD];
__device__ float g_ksum[OC];
__device__ float g_vsum[OC];
__device__ float g_kv[HH * DD * DD];
__device__ float g_scal[2];          // sumsq(q), sumsq(k)
__device__ float g_deg[NN];
__device__ int   g_offs[NN + 1];
__device__ int   g_cursor[NN];
__device__ int   g_src[EE];
__device__ float g_val[EE];

// ---------------- 0: zero scratch ----------------
__global__ void zero_kernel() {
    int i = blockIdx.x * 256 + threadIdx.x;
    if (i < NN) g_deg[i] = 0.f;
    if (i < HH * DD * DD) g_kv[i] = 0.f;
    if (i < OC) { g_ksum[i] = 0.f; g_vsum[i] = 0.f; }
    if (i < 2) g_scal[i] = 0.f;
}

// ---------------- tf32 helpers ----------------
__device__ __forceinline__ uint32_t f2tf32(float x) {
    uint32_t r;
    asm("cvt.rna.tf32.f32 %0, %1;" : "=r"(r) : "f"(x));
    return r;
}

__device__ __forceinline__ void mma_tf32(float& d0, float& d1, float& d2, float& d3,
                                         const uint32_t* a, const uint32_t* b) {
    asm volatile(
        "mma.sync.aligned.m16n8k8.row.col.f32.tf32.tf32.f32 "
        "{%0,%1,%2,%3}, {%4,%5,%6,%7}, {%8,%9}, {%0,%1,%2,%3};\n"
        : "+f"(d0), "+f"(d1), "+f"(d2), "+f"(d3)
        : "r"(a[0]), "r"(a[1]), "r"(a[2]), "r"(a[3]), "r"(b[0]), "r"(b[1]));
}

// ---------------- 1: fused QKV GEMM (tf32 tensor cores) ----------------
// O[m,n] = sum_k X[m,k] * W[n,k] + b[n]
// block = 256 thr (8 warps, 2x4), 128x128 output tile, BK=32.
#define BK 32
#define APAD 36   // padded smem row stride (floats) -> conflict-free frag loads

__global__ void __launch_bounds__(256, 2)
gemm_qkv(const float* __restrict__ Xq, const float* __restrict__ Xs,
         const float* __restrict__ Wq, const float* __restrict__ bq,
         const float* __restrict__ Wk, const float* __restrict__ bk,
         const float* __restrict__ Wv, const float* __restrict__ bv)
{
    __shared__ uint32_t As[128 * APAD];
    __shared__ uint32_t Bs[128 * APAD];

    int t = threadIdx.x;
    int bm = blockIdx.y;           // 0..390
    int bn = blockIdx.x;           // 0..5
    int which = bn >> 1;
    const float* X = (which == 0) ? Xq : Xs;
    const float* W = (which == 0) ? Wq : (which == 1 ? Wk : Wv);
    const float* B = (which == 0) ? bq : (which == 1 ? bk : bv);
    float* O = (which == 0) ? g_q : (which == 1 ? g_k : g_v);
    int n0 = (bn & 1) * 128;
    int m0 = bm * 128;

    int lane = t & 31;
    int warp = t >> 5;
    int wm = warp & 1;             // 0..1 -> 64 rows
    int wn = warp >> 1;            // 0..3 -> 32 cols

    // global->smem mapping: 32 rows x 32 cols per pass, 4 passes
    int lr = t >> 3;               // 0..31
    int lc = (t & 7) * 4;          // 0,4,...,28

    float d[4][4][4];
#pragma unroll
    for (int i = 0; i < 4; i++)
#pragma unroll
        for (int j = 0; j < 4; j++)
#pragma unroll
            for (int c = 0; c < 4; c++) d[i][j][c] = 0.f;

    for (int k0 = 0; k0 < CC; k0 += BK) {
#pragma unroll
        for (int p = 0; p < 4; p++) {
            int r = p * 32 + lr;
            int gr = m0 + r;
            float4 xv = make_float4(0.f, 0.f, 0.f, 0.f);
            if (gr < NN) xv = *(const float4*)&X[(size_t)gr * CC + k0 + lc];
            uint4 u = make_uint4(f2tf32(xv.x), f2tf32(xv.y), f2tf32(xv.z), f2tf32(xv.w));
            *(uint4*)&As[r * APAD + lc] = u;
            float4 wv = *(const float4*)&W[(size_t)(n0 + r) * CC + k0 + lc];
            uint4 w = make_uint4(f2tf32(wv.x), f2tf32(wv.y), f2tf32(wv.z), f2tf32(wv.w));
            *(uint4*)&Bs[r * APAD + lc] = w;
        }
        __syncthreads();

#pragma unroll
        for (int kf = 0; kf < 4; kf++) {
            uint32_t a[4][4];
            int ka = kf * 8 + (lane & 3);
#pragma unroll
            for (int mf = 0; mf < 4; mf++) {
                int ra = wm * 64 + mf * 16 + (lane >> 2);
                a[mf][0] = As[ra * APAD + ka];
                a[mf][1] = As[(ra + 8) * APAD + ka];
                a[mf][2] = As[ra * APAD + ka + 4];
                a[mf][3] = As[(ra + 8) * APAD + ka + 4];
            }
#pragma unroll
            for (int nf = 0; nf < 4; nf++) {
                int rb = wn * 32 + nf * 8 + (lane >> 2);
                uint32_t b[2];
                b[0] = Bs[rb * APAD + ka];
                b[1] = Bs[rb * APAD + ka + 4];
#pragma unroll
                for (int mf = 0; mf < 4; mf++)
                    mma_tf32(d[mf][nf][0], d[mf][nf][1], d[mf][nf][2], d[mf][nf][3],
                             a[mf], b);
            }
        }
        __syncthreads();
    }

    // epilogue: bias + store (float2 per pair of cols)
#pragma unroll
    for (int mf = 0; mf < 4; mf++) {
#pragma unroll
        for (int nf = 0; nf < 4; nf++) {
            int row = m0 + wm * 64 + mf * 16 + (lane >> 2);
            int col = n0 + wn * 32 + nf * 8 + (lane & 3) * 2;
            float bi0 = B[col], bi1 = B[col + 1];
            if (row < NN) {
                float2 o = make_float2(d[mf][nf][0] + bi0, d[mf][nf][1] + bi1);
                *(float2*)&O[(size_t)row * OC + col] = o;
            }
            if (row + 8 < NN) {
                float2 o = make_float2(d[mf][nf][2] + bi0, d[mf][nf][3] + bi1);
                *(float2*)&O[(size_t)(row + 8) * OC + col] = o;
            }
        }
    }
}

// ---------------- 2a: column sums + Frobenius sumsq (barrier-free loop) ----------------
__global__ void colsum_kernel() {
    int b = blockIdx.x;      // 196
    int c = threadIdx.x;     // 256
    __shared__ float red[256];
    float qsq = 0.f, ksq = 0.f, ksa = 0.f, vsa = 0.f;
    int n0 = b * 256;
    int n1 = n0 + 256; if (n1 > NN) n1 = NN;
    for (int n = n0; n < n1; ++n) {
        float qv = g_q[(size_t)n * OC + c];
        float kv = g_k[(size_t)n * OC + c];
        float vv = g_v[(size_t)n * OC + c];
        qsq += qv * qv; ksq += kv * kv; ksa += kv; vsa += vv;
    }
    atomicAdd(&g_ksum[c], ksa);
    atomicAdd(&g_vsum[c], vsa);
    red[c] = qsq; __syncthreads();
    for (int s = 128; s > 0; s >>= 1) { if (c < s) red[c] += red[c + s]; __syncthreads(); }
    if (c == 0) atomicAdd(&g_scal[0], red[0]);
    __syncthreads();
    red[c] = ksq; __syncthreads();
    for (int s = 128; s > 0; s >>= 1) { if (c < s) red[c] += red[c + s]; __syncthreads(); }
    if (c == 0) atomicAdd(&g_scal[1], red[0]);
}

// ---------------- 2b: vbar[n,d] = mean over heads of v ----------------
__global__ void vbar_kernel() {
    int i = blockIdx.x * 256 + threadIdx.x;
    if (i >= NN * DD) return;
    int n = i >> 6, dd = i & 63;
    const float* vp = &g_v[(size_t)n * OC + dd];
    g_vbar[i] = 0.25f * (vp[0] + vp[64] + vp[128] + vp[192]);
}

// ---------------- 3: kv[h][m][d] = sum_n k[n,h,m]*v[n,h,d] ----------------
// 64x64 smem tiles, 16x16 thread grid, 4x4 register blocking.
__global__ void __launch_bounds__(256)
kv_kernel() {
    __shared__ float sk[64][64];
    __shared__ float sw[64][64];
    int t = threadIdx.x;
    int h = blockIdx.y;
    int base = blockIdx.x * 512;
    int ty = t >> 4, tx = t & 15;
    int lr = t >> 4;             // 0..15
    int lc = (t & 15) * 4;       // 0..60

    float acc[4][4];
#pragma unroll
    for (int i = 0; i < 4; i++)
#pragma unroll
        for (int j = 0; j < 4; j++) acc[i][j] = 0.f;

    for (int sub = 0; sub < 512; sub += 64) {
#pragma unroll
        for (int p = 0; p < 4; p++) {
            int r = p * 16 + lr;
            int n = base + sub + r;
            float4 kvv = make_float4(0.f, 0.f, 0.f, 0.f);
            float4 vvv = make_float4(0.f, 0.f, 0.f, 0.f);
            if (n < NN) {
                kvv = *(const float4*)&g_k[(size_t)n * OC + h * 64 + lc];
                vvv = *(const float4*)&g_v[(size_t)n * OC + h * 64 + lc];
            }
            *(float4*)&sk[r][lc] = kvv;
            *(float4*)&sw[r][lc] = vvv;
        }
        __syncthreads();
#pragma unroll 16
        for (int r = 0; r < 64; r++) {
            float4 ka = *(float4*)&sk[r][ty * 4];
            float4 vb = *(float4*)&sw[r][tx * 4];
            acc[0][0] += ka.x * vb.x; acc[0][1] += ka.x * vb.y;
            acc[0][2] += ka.x * vb.z; acc[0][3] += ka.x * vb.w;
            acc[1][0] += ka.y * vb.x; acc[1][1] += ka.y * vb.y;
            acc[1][2] += ka.y * vb.z; acc[1][3] += ka.y * vb.w;
            acc[2][0] += ka.z * vb.x; acc[2][1] += ka.z * vb.y;
            acc[2][2] += ka.z * vb.z; acc[2][3] += ka.z * vb.w;
            acc[3][0] += ka.w * vb.x; acc[3][1] += ka.w * vb.y;
            acc[3][2] += ka.w * vb.z; acc[3][3] += ka.w * vb.w;
        }
        __syncthreads();
    }
#pragma unroll
    for (int i = 0; i < 4; i++)
#pragma unroll
        for (int j = 0; j < 4; j++)
            atomicAdd(&g_kv[h * 4096 + (ty * 4 + i) * 64 + tx * 4 + j], acc[i][j]);
}

// ---------------- 4: degree on col ----------------
__global__ void degree_kernel(const int* __restrict__ ei) {
    int e = blockIdx.x * 256 + threadIdx.x;
    if (e < EE) atomicAdd(&g_deg[ei[EE + e]], 1.0f);
}

// ---------------- 5: exclusive scan of degrees (shuffle-based, 1 block) ----------------
__global__ void scan_kernel() {
    int t = threadIdx.x;                  // 1024
    const int PER = (NN + 1023) / 1024;   // 49
    int start = t * PER;
    int sum = 0;
    for (int i = 0; i < PER; i++) {
        int idx = start + i;
        if (idx < NN) sum += (int)g_deg[idx];
    }
    int lane = t & 31, w = t >> 5;
    int v = sum;
#pragma unroll
    for (int off = 1; off < 32; off <<= 1) {
        int y = __shfl_up_sync(0xffffffffu, v, off);
        if (lane >= off) v += y;
    }
    __shared__ int wsum[32];
    if (lane == 31) wsum[w] = v;
    __syncthreads();
    if (w == 0) {
        int x = wsum[lane];
#pragma unroll
        for (int off = 1; off < 32; off <<= 1) {
            int y = __shfl_up_sync(0xffffffffu, x, off);
            if (lane >= off) x += y;
        }
        wsum[lane] = x;
    }
    __syncthreads();
    int excl = v - sum + ((w > 0) ? wsum[w - 1] : 0);
    int run = excl;
    for (int i = 0; i < PER; i++) {
        int idx = start + i;
        if (idx < NN) {
            int dcur = (int)g_deg[idx];
            g_offs[idx] = run;
            g_cursor[idx] = run;
            run += dcur;
        }
    }
    if (t == 0) g_offs[NN] = wsum[31];
}

// ---------------- 6: scatter edges into CSR-by-destination ----------------
__global__ void scatter_kernel(const int* __restrict__ ei, const float* __restrict__ ew) {
    int e = blockIdx.x * 256 + threadIdx.x;
    if (e >= EE) return;
    int r = ei[e];
    int c = ei[EE + e];
    float dc = g_deg[c];
    float dr = g_deg[r];
    float w = ew[e];
    float val = (dr > 0.f) ? w * rsqrtf(dc * dr) : 0.f;
    int slot = atomicAdd(&g_cursor[c], 1);
    g_src[slot] = r;
    g_val[slot] = val;
}

// ---------------- 7: attention epilogue ----------------
__global__ void attn_kernel(float* __restrict__ out) {
    extern __shared__ float skv[];     // 16384 floats (64KB)
    __shared__ float sks[OC];
    __shared__ float svs[OC];
    __shared__ float sq[4][OC];
    int t = threadIdx.x;
    for (int i = t; i < HH * DD * DD; i += 256) skv[i] = g_kv[i];
    sks[t] = g_ksum[t];
    svs[t] = g_vsum[t];
    float scal = rsqrtf(g_scal[0]) * rsqrtf(g_scal[1]);
    __syncthreads();
    int g = t >> 6, dd = t & 63;
    int ngroups = (NN + 3) / 4;
    for (int grp = blockIdx.x; grp < ngroups; grp += gridDim.x) {
        int n = grp * 4 + g;
        if (n < NN) {
#pragma unroll
            for (int j = 0; j < 4; j++)
                sq[g][dd + j * 64] = g_q[(size_t)n * OC + dd + j * 64];
        }
        __syncthreads();
        if (n < NN) {
            float acc = 0.f;
#pragma unroll
            for (int h = 0; h < HH; h++) {
                float num = 0.f, den = 0.f;
                const float* kvp = &skv[h * 4096];
#pragma unroll
                for (int m = 0; m < 64; m++) {
                    float qm = sq[g][h * 64 + m];
                    num += qm * kvp[m * 64 + dd];
                    den += qm * sks[h * 64 + m];
                }
                acc += (scal * num + svs[h * 64 + dd]) / (scal * den + (float)NN);
            }
            out[(size_t)n * 64 + dd] = 0.25f * acc;
        }
        __syncthreads();
    }
}

// ---------------- 8: GCN gather (atomic-free), out += sum ----------------
__global__ void gather_kernel(float* __restrict__ out) {
    int t = threadIdx.x;
    int n = blockIdx.x * 4 + (t >> 6);
    int dd = t & 63;
    if (n >= NN) return;
    int e0 = g_offs[n], e1 = g_offs[n + 1];
    float acc = 0.f;
    for (int e = e0; e < e1; ++e) {
        int r = g_src[e];
        float val = g_val[e];
        acc += val * g_vbar[(size_t)r * 64 + dd];
    }
    out[(size_t)n * 64 + dd] += acc;
}

// ---------------- launch ----------------
extern "C" void kernel_launch(void* const* d_in, const int* in_sizes, int n_in,
                              void* d_out, int out_size) {
    const float* query = (const float*)d_in[0];
    const float* source = (const float*)d_in[1];
    const float* Wq = (const float*)d_in[2];
    const float* bq = (const float*)d_in[3];
    const float* Wk = (const float*)d_in[4];
    const float* bk = (const float*)d_in[5];
    const float* Wv = (const float*)d_in[6];
    const float* bv = (const float*)d_in[7];
    const int*   ei = (const int*)d_in[8];
    const float* ew = (const float*)d_in[9];
    float* out = (float*)d_out;

    cudaFuncSetAttribute(attn_kernel, cudaFuncAttributeMaxDynamicSharedMemorySize,
                         HH * DD * DD * (int)sizeof(float));

    zero_kernel<<<196, 256>>>();
    gemm_qkv<<<dim3(6, 391), 256>>>(query, source, Wq, bq, Wk, bk, Wv, bv);
    colsum_kernel<<<196, 256>>>();
    vbar_kernel<<<(NN * DD + 255) / 256, 256>>>();
    kv_kernel<<<dim3(98, 4), 256>>>();
    degree_kernel<<<(EE + 255) / 256, 256>>>(ei);
    scan_kernel<<<1, 1024>>>();
    scatter_kernel<<<(EE + 255) / 256, 256>>>(ei, ew);
    attn_kernel<<<444, 256, HH * DD * DD * sizeof(float)>>>(out);
    gather_kernel<<<(NN + 3) / 4, 256>>>(out);
}

// round 6
// speedup vs baseline: 5.8485x; 1.6652x over previous
#include <cuda_runtime.h>
#include <cuda_bf16.h>
#include <math.h>
#include <stdint.h>

#define NN 50000
#define CC 256
#define HH 4
#define DD 64
#define EE 800000
#define OC 256   // H*D

// ---------------- device scratch ----------------
__device__ float g_q[NN * CC];
__device__ float g_k[NN * CC];
__device__ float g_v[NN * CC];
__device__ float g_vbar[NN * DD];
__device__ float g_ksum[OC];
__device__ float g_vsum[OC];
__device__ float g_kv[HH * DD * DD];   // stored TRANSPOSED: [h][d][m]
__device__ float g_scal[2];            // sumsq(q), sumsq(k)
__device__ float g_deg[NN];
__device__ int   g_offs[NN + 1];
__device__ int   g_cursor[NN];
__device__ int   g_src[EE];
__device__ float g_val[EE];
__device__ int   g_part[256];

// ---------------- 0: zero scratch ----------------
__global__ void zero_kernel() {
    int i = blockIdx.x * 256 + threadIdx.x;
    if (i < NN) g_deg[i] = 0.f;
    if (i < HH * DD * DD) g_kv[i] = 0.f;
    if (i < OC) { g_ksum[i] = 0.f; g_vsum[i] = 0.f; }
    if (i < 2) g_scal[i] = 0.f;
}

// ---------------- tf32 helpers ----------------
__device__ __forceinline__ uint32_t f2tf32(float x) {
    uint32_t r;
    asm("cvt.rna.tf32.f32 %0, %1;" : "=r"(r) : "f"(x));
    return r;
}

__device__ __forceinline__ void mma_tf32(float& d0, float& d1, float& d2, float& d3,
                                         const uint32_t* a, const uint32_t* b) {
    asm volatile(
        "mma.sync.aligned.m16n8k8.row.col.f32.tf32.tf32.f32 "
        "{%0,%1,%2,%3}, {%4,%5,%6,%7}, {%8,%9}, {%0,%1,%2,%3};\n"
        : "+f"(d0), "+f"(d1), "+f"(d2), "+f"(d3)
        : "r"(a[0]), "r"(a[1]), "r"(a[2]), "r"(a[3]), "r"(b[0]), "r"(b[1]));
}

// ---------------- 1: fused QKV GEMM (tf32 MMA + cp.async double buffer) ----------------
// O[m,n] = sum_k X[m,k] * W[n,k] + b[n]; 128x128 tile, BK=32, 2 stages.
#define BK 32
#define AST 36              // padded smem row stride (floats)
#define TSZ (128 * AST)     // one stage of one operand

__global__ void __launch_bounds__(256)
gemm_qkv(const float* __restrict__ Xq, const float* __restrict__ Xs,
         const float* __restrict__ Wq, const float* __restrict__ bq,
         const float* __restrict__ Wk, const float* __restrict__ bk,
         const float* __restrict__ Wv, const float* __restrict__ bv)
{
    extern __shared__ uint32_t sm[];
    uint32_t* As = sm;                 // [2][TSZ] raw fp32 bits
    uint32_t* Bs = sm + 2 * TSZ;       // [2][TSZ]

    int t = threadIdx.x;
    int bm = blockIdx.y;
    int bn = blockIdx.x;
    int which = bn >> 1;
    const float* X = (which == 0) ? Xq : Xs;
    const float* W = (which == 0) ? Wq : (which == 1 ? Wk : Wv);
    const float* B = (which == 0) ? bq : (which == 1 ? bk : bv);
    float* O = (which == 0) ? g_q : (which == 1 ? g_k : g_v);
    int n0 = (bn & 1) * 128;
    int m0 = bm * 128;

    int lane = t & 31;
    int warp = t >> 5;
    int wm = warp & 1;
    int wn = warp >> 1;

    int lr = t >> 3;              // 0..31
    int lc = (t & 7) * 4;         // 0..28

    auto load_tile = [&](int stage, int k0) {
#pragma unroll
        for (int p = 0; p < 4; p++) {
            int r = p * 32 + lr;
            int gr = m0 + r;
            int ok = (gr < NN);
            const float* srcA = X + (size_t)(ok ? gr : 0) * CC + k0 + lc;
            uint32_t da = (uint32_t)__cvta_generic_to_shared(&As[stage * TSZ + r * AST + lc]);
            int szA = ok ? 16 : 0;
            asm volatile("cp.async.cg.shared.global [%0], [%1], 16, %2;\n"
                         :: "r"(da), "l"(srcA), "r"(szA));
            const float* srcB = W + (size_t)(n0 + r) * CC + k0 + lc;
            uint32_t db = (uint32_t)__cvta_generic_to_shared(&Bs[stage * TSZ + r * AST + lc]);
            asm volatile("cp.async.cg.shared.global [%0], [%1], 16;\n"
                         :: "r"(db), "l"(srcB));
        }
        asm volatile("cp.async.commit_group;\n");
    };

    float d[4][4][4];
#pragma unroll
    for (int i = 0; i < 4; i++)
#pragma unroll
        for (int j = 0; j < 4; j++)
#pragma unroll
            for (int c = 0; c < 4; c++) d[i][j][c] = 0.f;

    load_tile(0, 0);

    for (int ki = 0; ki < CC / BK; ki++) {
        if (ki < CC / BK - 1) {
            load_tile((ki + 1) & 1, (ki + 1) * BK);
            asm volatile("cp.async.wait_group 1;\n");
        } else {
            asm volatile("cp.async.wait_group 0;\n");
        }
        __syncthreads();

        const float* Af = (const float*)&As[(ki & 1) * TSZ];
        const float* Bf = (const float*)&Bs[(ki & 1) * TSZ];
#pragma unroll
        for (int kf = 0; kf < 4; kf++) {
            uint32_t a[4][4];
            int ka = kf * 8 + (lane & 3);
#pragma unroll
            for (int mf = 0; mf < 4; mf++) {
                int ra = wm * 64 + mf * 16 + (lane >> 2);
                a[mf][0] = f2tf32(Af[ra * AST + ka]);
                a[mf][1] = f2tf32(Af[(ra + 8) * AST + ka]);
                a[mf][2] = f2tf32(Af[ra * AST + ka + 4]);
                a[mf][3] = f2tf32(Af[(ra + 8) * AST + ka + 4]);
            }
#pragma unroll
            for (int nf = 0; nf < 4; nf++) {
                int rb = wn * 32 + nf * 8 + (lane >> 2);
                uint32_t b[2];
                b[0] = f2tf32(Bf[rb * AST + ka]);
                b[1] = f2tf32(Bf[rb * AST + ka + 4]);
#pragma unroll
                for (int mf = 0; mf < 4; mf++)
                    mma_tf32(d[mf][nf][0], d[mf][nf][1], d[mf][nf][2], d[mf][nf][3],
                             a[mf], b);
            }
        }
        __syncthreads();
    }

#pragma unroll
    for (int mf = 0; mf < 4; mf++) {
#pragma unroll
        for (int nf = 0; nf < 4; nf++) {
            int row = m0 + wm * 64 + mf * 16 + (lane >> 2);
            int col = n0 + wn * 32 + nf * 8 + (lane & 3) * 2;
            float bi0 = B[col], bi1 = B[col + 1];
            if (row < NN) {
                float2 o = make_float2(d[mf][nf][0] + bi0, d[mf][nf][1] + bi1);
                *(float2*)&O[(size_t)row * OC + col] = o;
            }
            if (row + 8 < NN) {
                float2 o = make_float2(d[mf][nf][2] + bi0, d[mf][nf][3] + bi1);
                *(float2*)&O[(size_t)(row + 8) * OC + col] = o;
            }
        }
    }
}

// ---------------- 2a: column sums + Frobenius sumsq ----------------
__global__ void colsum_kernel() {
    int b = blockIdx.x;      // 196
    int c = threadIdx.x;     // 256
    __shared__ float red[256];
    float qsq = 0.f, ksq = 0.f, ksa = 0.f, vsa = 0.f;
    int n0 = b * 256;
    int n1 = n0 + 256; if (n1 > NN) n1 = NN;
    for (int n = n0; n < n1; ++n) {
        float qv = g_q[(size_t)n * OC + c];
        float kv = g_k[(size_t)n * OC + c];
        float vv = g_v[(size_t)n * OC + c];
        qsq += qv * qv; ksq += kv * kv; ksa += kv; vsa += vv;
    }
    atomicAdd(&g_ksum[c], ksa);
    atomicAdd(&g_vsum[c], vsa);
    red[c] = qsq; __syncthreads();
    for (int s = 128; s > 0; s >>= 1) { if (c < s) red[c] += red[c + s]; __syncthreads(); }
    if (c == 0) atomicAdd(&g_scal[0], red[0]);
    __syncthreads();
    red[c] = ksq; __syncthreads();
    for (int s = 128; s > 0; s >>= 1) { if (c < s) red[c] += red[c + s]; __syncthreads(); }
    if (c == 0) atomicAdd(&g_scal[1], red[0]);
}

// ---------------- 2b: vbar[n,d] = mean over heads of v ----------------
__global__ void vbar_kernel() {
    int i = blockIdx.x * 256 + threadIdx.x;
    if (i >= NN * DD) return;
    int n = i >> 6, dd = i & 63;
    const float* vp = &g_v[(size_t)n * OC + dd];
    g_vbar[i] = 0.25f * (vp[0] + vp[64] + vp[128] + vp[192]);
}

// ---------------- 3: kv[h][d][m] = sum_n k[n,h,m]*v[n,h,d]  (TRANSPOSED store) ----------------
__global__ void __launch_bounds__(256)
kv_kernel() {
    __shared__ float sk[64][64];
    __shared__ float sw[64][64];
    int t = threadIdx.x;
    int h = blockIdx.y;
    int base = blockIdx.x * 512;
    int ty = t >> 4, tx = t & 15;
    int lr = t >> 4;
    int lc = (t & 15) * 4;

    float acc[4][4];
#pragma unroll
    for (int i = 0; i < 4; i++)
#pragma unroll
        for (int j = 0; j < 4; j++) acc[i][j] = 0.f;

    for (int sub = 0; sub < 512; sub += 64) {
#pragma unroll
        for (int p = 0; p < 4; p++) {
            int r = p * 16 + lr;
            int n = base + sub + r;
            float4 kvv = make_float4(0.f, 0.f, 0.f, 0.f);
            float4 vvv = make_float4(0.f, 0.f, 0.f, 0.f);
            if (n < NN) {
                kvv = *(const float4*)&g_k[(size_t)n * OC + h * 64 + lc];
                vvv = *(const float4*)&g_v[(size_t)n * OC + h * 64 + lc];
            }
            *(float4*)&sk[r][lc] = kvv;
            *(float4*)&sw[r][lc] = vvv;
        }
        __syncthreads();
#pragma unroll 16
        for (int r = 0; r < 64; r++) {
            float4 ka = *(float4*)&sk[r][ty * 4];
            float4 vb = *(float4*)&sw[r][tx * 4];
            acc[0][0] += ka.x * vb.x; acc[0][1] += ka.x * vb.y;
            acc[0][2] += ka.x * vb.z; acc[0][3] += ka.x * vb.w;
            acc[1][0] += ka.y * vb.x; acc[1][1] += ka.y * vb.y;
            acc[1][2] += ka.y * vb.z; acc[1][3] += ka.y * vb.w;
            acc[2][0] += ka.z * vb.x; acc[2][1] += ka.z * vb.y;
            acc[2][2] += ka.z * vb.z; acc[2][3] += ka.z * vb.w;
            acc[3][0] += ka.w * vb.x; acc[3][1] += ka.w * vb.y;
            acc[3][2] += ka.w * vb.z; acc[3][3] += ka.w * vb.w;
        }
        __syncthreads();
    }
    // store transposed: [h][d][m], d = tx*4+j, m = ty*4+i
#pragma unroll
    for (int i = 0; i < 4; i++)
#pragma unroll
        for (int j = 0; j < 4; j++)
            atomicAdd(&g_kv[h * 4096 + (tx * 4 + j) * 64 + ty * 4 + i], acc[i][j]);
}

// ---------------- 4: degree on col ----------------
__global__ void degree_kernel(const int* __restrict__ ei) {
    int e = blockIdx.x * 256 + threadIdx.x;
    if (e < EE) atomicAdd(&g_deg[ei[EE + e]], 1.0f);
}

// ---------------- 5: parallel exclusive scan of degrees (3 kernels) ----------------
__global__ void scan1_kernel() {
    int b = blockIdx.x, t = threadIdx.x;
    int i = b * 256 + t;
    int v = (i < NN) ? (int)g_deg[i] : 0;
#pragma unroll
    for (int off = 16; off > 0; off >>= 1) v += __shfl_xor_sync(0xffffffffu, v, off);
    __shared__ int ws[8];
    if ((t & 31) == 0) ws[t >> 5] = v;
    __syncthreads();
    if (t == 0) {
        int s = 0;
#pragma unroll
        for (int j = 0; j < 8; j++) s += ws[j];
        g_part[b] = s;
    }
}

__global__ void scan2_kernel() {
    int t = threadIdx.x;         // 256
    int v = (t < 196) ? g_part[t] : 0;
    int lane = t & 31, w = t >> 5;
    int x = v;
#pragma unroll
    for (int off = 1; off < 32; off <<= 1) {
        int y = __shfl_up_sync(0xffffffffu, x, off);
        if (lane >= off) x += y;
    }
    __shared__ int ws[8];
    if (lane == 31) ws[w] = x;
    __syncthreads();
    if (t == 0) {
        int c = 0;
#pragma unroll
        for (int j = 0; j < 8; j++) { int tmp = ws[j]; ws[j] = c; c += tmp; }
    }
    __syncthreads();
    int incl = x + ws[w];
    if (t < 196) g_part[t] = incl - v;   // exclusive block offsets
    if (t == 0) g_offs[NN] = EE;
}

__global__ void scan3_kernel() {
    int b = blockIdx.x, t = threadIdx.x;
    int i = b * 256 + t;
    int v = (i < NN) ? (int)g_deg[i] : 0;
    int lane = t & 31, w = t >> 5;
    int x = v;
#pragma unroll
    for (int off = 1; off < 32; off <<= 1) {
        int y = __shfl_up_sync(0xffffffffu, x, off);
        if (lane >= off) x += y;
    }
    __shared__ int ws[8];
    if (lane == 31) ws[w] = x;
    __syncthreads();
    if (t == 0) {
        int c = 0;
#pragma unroll
        for (int j = 0; j < 8; j++) { int tmp = ws[j]; ws[j] = c; c += tmp; }
    }
    __syncthreads();
    int excl = (x - v) + ws[w] + g_part[b];
    if (i < NN) { g_offs[i] = excl; g_cursor[i] = excl; }
}

// ---------------- 6: scatter edges into CSR-by-destination ----------------
__global__ void scatter_kernel(const int* __restrict__ ei, const float* __restrict__ ew) {
    int e = blockIdx.x * 256 + threadIdx.x;
    if (e >= EE) return;
    int r = ei[e];
    int c = ei[EE + e];
    float dc = g_deg[c];
    float dr = g_deg[r];
    float w = ew[e];
    float val = (dr > 0.f) ? w * rsqrtf(dc * dr) : 0.f;
    int slot = atomicAdd(&g_cursor[c], 1);
    g_src[slot] = r;
    g_val[slot] = val;
}

// ---------------- 7: attention epilogue via tf32 MMA ----------------
// out[n,d] = 0.25 * sum_h (scal*num_h[n,d] + vsum[h,d]) / (scal*(q_nh . ksum_h) + N)
// num_h = q[:,h,:] @ kv[h]   (kv stored [h][d][m], i.e. B in [N,K] layout for row.col mma)
#define QST 68

__global__ void __launch_bounds__(256)
attn_kernel(float* __restrict__ out) {
    extern __shared__ uint32_t sm[];
    uint32_t* sq  = sm;                    // 128 x QST (tf32 bits)
    uint32_t* skv = sm + 128 * QST;        // 64 x QST
    float* sden = (float*)(skv + 64 * QST);  // 128
    float* sks  = sden + 128;                // 64
    float* svs  = sks + 64;                  // 64

    int t = threadIdx.x;
    int lane = t & 31, warp = t >> 5;
    int wm = warp >> 1;        // 0..3, 32-row band
    int wn = warp & 1;         // 0..1, 32-col band
    int m0 = blockIdx.x * 128;
    float scal = rsqrtf(g_scal[0]) * rsqrtf(g_scal[1]);

    float facc[2][4][4];
#pragma unroll
    for (int i = 0; i < 2; i++)
#pragma unroll
        for (int j = 0; j < 4; j++)
#pragma unroll
            for (int c = 0; c < 4; c++) facc[i][j][c] = 0.f;

    for (int h = 0; h < HH; h++) {
        __syncthreads();
        {
            int r = t >> 4;              // 0..15
            int c = (t & 15) * 4;
#pragma unroll
            for (int p = 0; p < 8; p++) {
                int row = p * 16 + r;
                int n = m0 + row;
                float4 v = make_float4(0.f, 0.f, 0.f, 0.f);
                if (n < NN) v = *(const float4*)&g_q[(size_t)n * OC + h * 64 + c];
                uint4 u = make_uint4(f2tf32(v.x), f2tf32(v.y), f2tf32(v.z), f2tf32(v.w));
                *(uint4*)&sq[row * QST + c] = u;
            }
#pragma unroll
            for (int p = 0; p < 4; p++) {
                int row = p * 16 + r;    // d index
                float4 v = *(const float4*)&g_kv[h * 4096 + row * 64 + c];
                uint4 u = make_uint4(f2tf32(v.x), f2tf32(v.y), f2tf32(v.z), f2tf32(v.w));
                *(uint4*)&skv[row * QST + c] = u;
            }
            if (t < 64) { sks[t] = g_ksum[h * 64 + t]; svs[t] = g_vsum[h * 64 + t]; }
        }
        __syncthreads();
        {   // denominator per row
            int r = t >> 1, p = t & 1;
            float s = 0.f;
#pragma unroll
            for (int m = 0; m < 32; m++)
                s += __uint_as_float(sq[r * QST + p * 32 + m]) * sks[p * 32 + m];
            s += __shfl_xor_sync(0xffffffffu, s, 1);
            if (p == 0) sden[r] = scal * s + (float)NN;
        }
        __syncthreads();

        float num[2][4][4];
#pragma unroll
        for (int i = 0; i < 2; i++)
#pragma unroll
            for (int j = 0; j < 4; j++)
#pragma unroll
                for (int c = 0; c < 4; c++) num[i][j][c] = 0.f;

#pragma unroll
        for (int kf = 0; kf < 8; kf++) {
            int ka = kf * 8 + (lane & 3);
            uint32_t a[2][4];
#pragma unroll
            for (int mf = 0; mf < 2; mf++) {
                int ra = wm * 32 + mf * 16 + (lane >> 2);
                a[mf][0] = sq[ra * QST + ka];
                a[mf][1] = sq[(ra + 8) * QST + ka];
                a[mf][2] = sq[ra * QST + ka + 4];
                a[mf][3] = sq[(ra + 8) * QST + ka + 4];
            }
#pragma unroll
            for (int nf = 0; nf < 4; nf++) {
                int rb = wn * 32 + nf * 8 + (lane >> 2);
                uint32_t b[2];
                b[0] = skv[rb * QST + ka];
                b[1] = skv[rb * QST + ka + 4];
#pragma unroll
                for (int mf = 0; mf < 2; mf++)
                    mma_tf32(num[mf][nf][0], num[mf][nf][1], num[mf][nf][2], num[mf][nf][3],
                             a[mf], b);
            }
        }
        // combine this head
#pragma unroll
        for (int mf = 0; mf < 2; mf++) {
            int rl = wm * 32 + mf * 16 + (lane >> 2);
            float i0 = 1.f / sden[rl];
            float i1 = 1.f / sden[rl + 8];
#pragma unroll
            for (int nf = 0; nf < 4; nf++) {
                int col = wn * 32 + nf * 8 + (lane & 3) * 2;
                float s0 = svs[col], s1 = svs[col + 1];
                facc[mf][nf][0] += (scal * num[mf][nf][0] + s0) * i0;
                facc[mf][nf][1] += (scal * num[mf][nf][1] + s1) * i0;
                facc[mf][nf][2] += (scal * num[mf][nf][2] + s0) * i1;
                facc[mf][nf][3] += (scal * num[mf][nf][3] + s1) * i1;
            }
        }
    }
    // store
#pragma unroll
    for (int mf = 0; mf < 2; mf++) {
#pragma unroll
        for (int nf = 0; nf < 4; nf++) {
            int row = m0 + wm * 32 + mf * 16 + (lane >> 2);
            int col = wn * 32 + nf * 8 + (lane & 3) * 2;
            if (row < NN)
                *(float2*)&out[(size_t)row * 64 + col] =
                    make_float2(0.25f * facc[mf][nf][0], 0.25f * facc[mf][nf][1]);
            if (row + 8 < NN)
                *(float2*)&out[(size_t)(row + 8) * 64 + col] =
                    make_float2(0.25f * facc[mf][nf][2], 0.25f * facc[mf][nf][3]);
        }
    }
}

// ---------------- 8: GCN gather (atomic-free), out += sum ----------------
__global__ void gather_kernel(float* __restrict__ out) {
    int t = threadIdx.x;
    int n = blockIdx.x * 4 + (t >> 6);
    int dd = t & 63;
    if (n >= NN) return;
    int e0 = g_offs[n], e1 = g_offs[n + 1];
    float acc = 0.f;
    for (int e = e0; e < e1; ++e) {
        int r = g_src[e];
        float val = g_val[e];
        acc += val * g_vbar[(size_t)r * 64 + dd];
    }
    out[(size_t)n * 64 + dd] += acc;
}

// ---------------- launch ----------------
extern "C" void kernel_launch(void* const* d_in, const int* in_sizes, int n_in,
                              void* d_out, int out_size) {
    const float* query = (const float*)d_in[0];
    const float* source = (const float*)d_in[1];
    const float* Wq = (const float*)d_in[2];
    const float* bq = (const float*)d_in[3];
    const float* Wk = (const float*)d_in[4];
    const float* bk = (const float*)d_in[5];
    const float* Wv = (const float*)d_in[6];
    const float* bv = (const float*)d_in[7];
    const int*   ei = (const int*)d_in[8];
    const float* ew = (const float*)d_in[9];
    float* out = (float*)d_out;

    const int gemm_smem = 4 * TSZ * (int)sizeof(uint32_t);             // 73728
    const int attn_smem = (128 * QST + 64 * QST) * 4 + (128 + 64 + 64) * 4;
    cudaFuncSetAttribute(gemm_qkv, cudaFuncAttributeMaxDynamicSharedMemorySize, gemm_smem);
    cudaFuncSetAttribute(attn_kernel, cudaFuncAttributeMaxDynamicSharedMemorySize, attn_smem);

    zero_kernel<<<196, 256>>>();
    gemm_qkv<<<dim3(6, 391), 256, gemm_smem>>>(query, source, Wq, bq, Wk, bk, Wv, bv);
    colsum_kernel<<<196, 256>>>();
    vbar_kernel<<<(NN * DD + 255) / 256, 256>>>();
    kv_kernel<<<dim3(98, 4), 256>>>();
    degree_kernel<<<(EE + 255) / 256, 256>>>(ei);
    scan1_kernel<<<196, 256>>>();
    scan2_kernel<<<1, 256>>>();
    scan3_kernel<<<196, 256>>>();
    scatter_kernel<<<(EE + 255) / 256, 256>>>(ei, ew);
    attn_kernel<<<391, 256, attn_smem>>>(out);
    gather_kernel<<<(NN + 3) / 4, 256>>>(out);
}

// round 7
// speedup vs baseline: 6.1742x; 1.0557x over previous
#include <cuda_runtime.h>
#include <cuda_bf16.h>
#include <math.h>
#include <stdint.h>

#define NN 50000
#define CC 256
#define HH 4
#define DD 64
#define EE 800000
#define OC 256   // H*D
#define FNN 50000.0f

// ---------------- device scratch ----------------
__device__ float g_q[NN * OC];
__device__ float g_vbar[NN * DD];
__device__ float g_S[OC * OC];       // Xs^T Xs (tiles (0,0),(0,1),(1,1) stored)
__device__ float g_T[OC * OC];       // Wk @ S
__device__ float g_xsum[OC];         // colsum of Xs
__device__ float g_wvbar[DD * CC];
__device__ float g_bvbar[DD];
__device__ float g_ksum[OC];
__device__ float g_vsum[OC];
__device__ float g_kv[HH * DD * DD]; // [h][d][m]
__device__ float g_scal[2];          // sumsq(q), sumsq(k)
__device__ float g_deg[NN];
__device__ int   g_offs[NN + 1];
__device__ int   g_cursor[NN];
__device__ int   g_src[EE];
__device__ float g_val[EE];
__device__ int   g_part[256];

// ---------------- helpers ----------------
__device__ __forceinline__ uint32_t f2tf32(float x) {
    uint32_t r;
    asm("cvt.rna.tf32.f32 %0, %1;" : "=r"(r) : "f"(x));
    return r;
}
__device__ __forceinline__ uint32_t pk(float lo, float hi) {
    uint32_t r;
    asm("cvt.rn.bf16x2.f32 %0, %1, %2;" : "=r"(r) : "f"(hi), "f"(lo));
    return r;
}
__device__ __forceinline__ void mma_tf32(float& d0, float& d1, float& d2, float& d3,
                                         const uint32_t* a, const uint32_t* b) {
    asm volatile(
        "mma.sync.aligned.m16n8k8.row.col.f32.tf32.tf32.f32 "
        "{%0,%1,%2,%3}, {%4,%5,%6,%7}, {%8,%9}, {%0,%1,%2,%3};\n"
        : "+f"(d0), "+f"(d1), "+f"(d2), "+f"(d3)
        : "r"(a[0]), "r"(a[1]), "r"(a[2]), "r"(a[3]), "r"(b[0]), "r"(b[1]));
}
__device__ __forceinline__ void mma_bf16(float& d0, float& d1, float& d2, float& d3,
                                         const uint32_t* a, const uint32_t* b) {
    asm volatile(
        "mma.sync.aligned.m16n8k16.row.col.f32.bf16.bf16.f32 "
        "{%0,%1,%2,%3}, {%4,%5,%6,%7}, {%8,%9}, {%0,%1,%2,%3};\n"
        : "+f"(d0), "+f"(d1), "+f"(d2), "+f"(d3)
        : "r"(a[0]), "r"(a[1]), "r"(a[2]), "r"(a[3]), "r"(b[0]), "r"(b[1]));
}

// ---------------- 0: zero scratch + Wvbar prep ----------------
__global__ void zero_kernel(const float* __restrict__ Wv, const float* __restrict__ bv) {
    int i = blockIdx.x * 256 + threadIdx.x;   // grid 256 -> 65536
    g_S[i] = 0.f;
    if (i < NN) g_deg[i] = 0.f;
    if (i < OC) g_xsum[i] = 0.f;
    if (i < 2) g_scal[i] = 0.f;
    if (i < DD * CC) {
        int d = i >> 8, c = i & 255;
        g_wvbar[i] = 0.25f * (Wv[(d) * CC + c] + Wv[(d + 64) * CC + c] +
                              Wv[(d + 128) * CC + c] + Wv[(d + 192) * CC + c]);
    }
    if (i < DD)
        g_bvbar[i] = 0.25f * (bv[i] + bv[i + 64] + bv[i + 128] + bv[i + 192]);
}

// ---------------- 1: Q GEMM (bf16 MMA + cp.async) + qsumsq epilogue ----------------
#define BK 32
#define AST 36
#define TSZ (128 * AST)

__global__ void __launch_bounds__(256)
gemm_q(const float* __restrict__ X, const float* __restrict__ W, const float* __restrict__ B)
{
    extern __shared__ float smf[];
    float* As = smf;
    float* Bs = smf + 2 * TSZ;
    __shared__ float red8[8];

    int t = threadIdx.x;
    int m0 = blockIdx.y * 128;
    int n0 = blockIdx.x * 128;
    int lane = t & 31, warp = t >> 5;
    int wm = warp & 1, wn = warp >> 1;
    int lr = t >> 3, lc = (t & 7) * 4;

    auto load_tile = [&](int stage, int k0) {
#pragma unroll
        for (int p = 0; p < 4; p++) {
            int r = p * 32 + lr;
            int gr = m0 + r;
            int ok = (gr < NN);
            const float* srcA = X + (size_t)(ok ? gr : 0) * CC + k0 + lc;
            uint32_t da = (uint32_t)__cvta_generic_to_shared(&As[stage * TSZ + r * AST + lc]);
            int szA = ok ? 16 : 0;
            asm volatile("cp.async.cg.shared.global [%0], [%1], 16, %2;\n"
                         :: "r"(da), "l"(srcA), "r"(szA));
            const float* srcB = W + (size_t)(n0 + r) * CC + k0 + lc;
            uint32_t db = (uint32_t)__cvta_generic_to_shared(&Bs[stage * TSZ + r * AST + lc]);
            asm volatile("cp.async.cg.shared.global [%0], [%1], 16;\n"
                         :: "r"(db), "l"(srcB));
        }
        asm volatile("cp.async.commit_group;\n");
    };

    float d[4][4][4];
#pragma unroll
    for (int i = 0; i < 4; i++)
#pragma unroll
        for (int j = 0; j < 4; j++)
#pragma unroll
            for (int c = 0; c < 4; c++) d[i][j][c] = 0.f;

    load_tile(0, 0);
    for (int ki = 0; ki < CC / BK; ki++) {
        if (ki < CC / BK - 1) {
            load_tile((ki + 1) & 1, (ki + 1) * BK);
            asm volatile("cp.async.wait_group 1;\n");
        } else {
            asm volatile("cp.async.wait_group 0;\n");
        }
        __syncthreads();
        const float* Af = As + (ki & 1) * TSZ;
        const float* Bf = Bs + (ki & 1) * TSZ;
#pragma unroll
        for (int kf = 0; kf < 2; kf++) {
            int ka = kf * 16 + (lane & 3) * 2;
            uint32_t a[4][4], b[4][2];
#pragma unroll
            for (int mf = 0; mf < 4; mf++) {
                int ra = wm * 64 + mf * 16 + (lane >> 2);
                float2 x0 = *(const float2*)&Af[ra * AST + ka];
                float2 x1 = *(const float2*)&Af[(ra + 8) * AST + ka];
                float2 x2 = *(const float2*)&Af[ra * AST + ka + 8];
                float2 x3 = *(const float2*)&Af[(ra + 8) * AST + ka + 8];
                a[mf][0] = pk(x0.x, x0.y); a[mf][1] = pk(x1.x, x1.y);
                a[mf][2] = pk(x2.x, x2.y); a[mf][3] = pk(x3.x, x3.y);
            }
#pragma unroll
            for (int nf = 0; nf < 4; nf++) {
                int rb = wn * 32 + nf * 8 + (lane >> 2);
                float2 y0 = *(const float2*)&Bf[rb * AST + ka];
                float2 y1 = *(const float2*)&Bf[rb * AST + ka + 8];
                b[nf][0] = pk(y0.x, y0.y); b[nf][1] = pk(y1.x, y1.y);
            }
#pragma unroll
            for (int nf = 0; nf < 4; nf++)
#pragma unroll
                for (int mf = 0; mf < 4; mf++)
                    mma_bf16(d[mf][nf][0], d[mf][nf][1], d[mf][nf][2], d[mf][nf][3],
                             a[mf], b[nf]);
        }
        __syncthreads();
    }

    float qs = 0.f;
#pragma unroll
    for (int mf = 0; mf < 4; mf++) {
#pragma unroll
        for (int nf = 0; nf < 4; nf++) {
            int row = m0 + wm * 64 + mf * 16 + (lane >> 2);
            int col = n0 + wn * 32 + nf * 8 + (lane & 3) * 2;
            float bi0 = B[col], bi1 = B[col + 1];
            if (row < NN) {
                float o0 = d[mf][nf][0] + bi0, o1 = d[mf][nf][1] + bi1;
                *(float2*)&g_q[(size_t)row * OC + col] = make_float2(o0, o1);
                qs += o0 * o0 + o1 * o1;
            }
            if (row + 8 < NN) {
                float o0 = d[mf][nf][2] + bi0, o1 = d[mf][nf][3] + bi1;
                *(float2*)&g_q[(size_t)(row + 8) * OC + col] = make_float2(o0, o1);
                qs += o0 * o0 + o1 * o1;
            }
        }
    }
#pragma unroll
    for (int off = 16; off > 0; off >>= 1) qs += __shfl_xor_sync(0xffffffffu, qs, off);
    if (lane == 0) red8[warp] = qs;
    __syncthreads();
    if (t == 0) {
        float s = 0.f;
#pragma unroll
        for (int j = 0; j < 8; j++) s += red8[j];
        atomicAdd(&g_scal[0], s);
    }
}

// ---------------- 2: vbar GEMM (tf32, 128x64 tile) + xsum fold ----------------
__global__ void __launch_bounds__(256)
gemm_vbar(const float* __restrict__ Xs)
{
    extern __shared__ float smf[];
    float* As = smf;                  // [2][128*AST]
    float* Bs = smf + 2 * TSZ;        // [2][64*AST]

    int t = threadIdx.x;
    int m0 = blockIdx.x * 128;
    int lane = t & 31, warp = t >> 5;
    int lr = t >> 3, lc = (t & 7) * 4;

    auto load_tile = [&](int stage, int k0) {
#pragma unroll
        for (int p = 0; p < 4; p++) {
            int r = p * 32 + lr;
            int gr = m0 + r;
            int ok = (gr < NN);
            const float* srcA = Xs + (size_t)(ok ? gr : 0) * CC + k0 + lc;
            uint32_t da = (uint32_t)__cvta_generic_to_shared(&As[stage * TSZ + r * AST + lc]);
            int szA = ok ? 16 : 0;
            asm volatile("cp.async.cg.shared.global [%0], [%1], 16, %2;\n"
                         :: "r"(da), "l"(srcA), "r"(szA));
        }
#pragma unroll
        for (int p = 0; p < 2; p++) {
            int r = p * 32 + lr;          // 0..63
            const float* srcB = g_wvbar + (size_t)r * CC + k0 + lc;
            uint32_t db = (uint32_t)__cvta_generic_to_shared(&Bs[stage * 64 * AST + r * AST + lc]);
            asm volatile("cp.async.cg.shared.global [%0], [%1], 16;\n"
                         :: "r"(db), "l"(srcB));
        }
        asm volatile("cp.async.commit_group;\n");
    };

    float acc[8][4];
#pragma unroll
    for (int i = 0; i < 8; i++)
#pragma unroll
        for (int c = 0; c < 4; c++) acc[i][c] = 0.f;

    load_tile(0, 0);
    for (int ki = 0; ki < CC / BK; ki++) {
        if (ki < CC / BK - 1) {
            load_tile((ki + 1) & 1, (ki + 1) * BK);
            asm volatile("cp.async.wait_group 1;\n");
        } else {
            asm volatile("cp.async.wait_group 0;\n");
        }
        __syncthreads();
        const float* Af = As + (ki & 1) * TSZ;
        const float* Bf = Bs + (ki & 1) * 64 * AST;

        {   // xsum fold: column sums of this A tile
            int col = t & 31, rg = t >> 5;
            float p = 0.f;
#pragma unroll
            for (int r = 0; r < 16; r++) p += Af[(rg * 16 + r) * AST + col];
            atomicAdd(&g_xsum[ki * 32 + col], p);
        }
#pragma unroll
        for (int kf = 0; kf < 4; kf++) {
            int ka = kf * 8 + (lane & 3);
            uint32_t a[4];
            int ra = warp * 16 + (lane >> 2);
            a[0] = f2tf32(Af[ra * AST + ka]);
            a[1] = f2tf32(Af[(ra + 8) * AST + ka]);
            a[2] = f2tf32(Af[ra * AST + ka + 4]);
            a[3] = f2tf32(Af[(ra + 8) * AST + ka + 4]);
#pragma unroll
            for (int nf = 0; nf < 8; nf++) {
                int rb = nf * 8 + (lane >> 2);
                uint32_t b[2];
                b[0] = f2tf32(Bf[rb * AST + ka]);
                b[1] = f2tf32(Bf[rb * AST + ka + 4]);
                mma_tf32(acc[nf][0], acc[nf][1], acc[nf][2], acc[nf][3], a, b);
            }
        }
        __syncthreads();
    }
#pragma unroll
    for (int nf = 0; nf < 8; nf++) {
        int row = m0 + warp * 16 + (lane >> 2);
        int col = nf * 8 + (lane & 3) * 2;
        float b0 = g_bvbar[col], b1 = g_bvbar[col + 1];
        if (row < NN)
            *(float2*)&g_vbar[(size_t)row * DD + col] =
                make_float2(acc[nf][0] + b0, acc[nf][1] + b1);
        if (row + 8 < NN)
            *(float2*)&g_vbar[(size_t)(row + 8) * DD + col] =
                make_float2(acc[nf][2] + b0, acc[nf][3] + b1);
    }
}

// ---------------- 3: SYRK  S = Xs^T Xs (bf16 MMA), tiles (0,0),(0,1),(1,1) ----------------
#define SST 132
#define CHK 1024
#define NCH 49            // 49*1024 = 50176 >= NN

__global__ void __launch_bounds__(256)
syrk_kernel(const float* __restrict__ Xs)
{
    extern __shared__ float smf[];
    float* Ai = smf;                      // [2][32*SST]
    float* Bj = smf + 2 * 32 * SST;       // [2][32*SST]

    int t = threadIdx.x;
    int chunk = blockIdx.x;
    int tile = blockIdx.y;                // 0:(0,0) 1:(0,1) 2:(1,1)
    int ci = (tile == 2) ? 1 : 0;
    int cj = (tile == 0) ? 0 : 1;
    int diag = (ci == cj);
    int nbase = chunk * CHK;
    int lane = t & 31, warp = t >> 5;
    int wm = warp & 1, wn = warp >> 1;

    auto load_tile = [&](int stage, int s) {
#pragma unroll
        for (int p = 0; p < 4; p++) {
            int idx = p * 256 + t;
            int r = idx >> 5;
            int c4 = (idx & 31) * 4;
            int node = nbase + s + r;
            int ok = (node < NN);
            const float* srcA = Xs + (size_t)(ok ? node : 0) * CC + ci * 128 + c4;
            uint32_t da = (uint32_t)__cvta_generic_to_shared(&Ai[stage * 32 * SST + r * SST + c4]);
            int sz = ok ? 16 : 0;
            asm volatile("cp.async.cg.shared.global [%0], [%1], 16, %2;\n"
                         :: "r"(da), "l"(srcA), "r"(sz));
            if (!diag) {
                const float* srcB = Xs + (size_t)(ok ? node : 0) * CC + cj * 128 + c4;
                uint32_t db = (uint32_t)__cvta_generic_to_shared(&Bj[stage * 32 * SST + r * SST + c4]);
                asm volatile("cp.async.cg.shared.global [%0], [%1], 16, %2;\n"
                             :: "r"(db), "l"(srcB), "r"(sz));
            }
        }
        asm volatile("cp.async.commit_group;\n");
    };

    float d[4][4][4];
#pragma unroll
    for (int i = 0; i < 4; i++)
#pragma unroll
        for (int j = 0; j < 4; j++)
#pragma unroll
            for (int c = 0; c < 4; c++) d[i][j][c] = 0.f;

    load_tile(0, 0);
    for (int si = 0; si < CHK / 32; si++) {
        if (si < CHK / 32 - 1) {
            load_tile((si + 1) & 1, (si + 1) * 32);
            asm volatile("cp.async.wait_group 1;\n");
        } else {
            asm volatile("cp.async.wait_group 0;\n");
        }
        __syncthreads();
        const float* Af = Ai + (si & 1) * 32 * SST;
        const float* Bf = diag ? Af : (Bj + (si & 1) * 32 * SST);
#pragma unroll
        for (int kf = 0; kf < 2; kf++) {
            int k = kf * 16 + (lane & 3) * 2;
            uint32_t a[4][4], b[4][2];
#pragma unroll
            for (int mf = 0; mf < 4; mf++) {
                int ra = wm * 64 + mf * 16 + (lane >> 2);
                a[mf][0] = pk(Af[k * SST + ra],       Af[(k + 1) * SST + ra]);
                a[mf][1] = pk(Af[k * SST + ra + 8],   Af[(k + 1) * SST + ra + 8]);
                a[mf][2] = pk(Af[(k + 8) * SST + ra], Af[(k + 9) * SST + ra]);
                a[mf][3] = pk(Af[(k + 8) * SST + ra + 8], Af[(k + 9) * SST + ra + 8]);
            }
#pragma unroll
            for (int nf = 0; nf < 4; nf++) {
                int rb = wn * 32 + nf * 8 + (lane >> 2);
                b[nf][0] = pk(Bf[k * SST + rb],       Bf[(k + 1) * SST + rb]);
                b[nf][1] = pk(Bf[(k + 8) * SST + rb], Bf[(k + 9) * SST + rb]);
            }
#pragma unroll
            for (int nf = 0; nf < 4; nf++)
#pragma unroll
                for (int mf = 0; mf < 4; mf++)
                    mma_bf16(d[mf][nf][0], d[mf][nf][1], d[mf][nf][2], d[mf][nf][3],
                             a[mf], b[nf]);
        }
        __syncthreads();
    }
#pragma unroll
    for (int mf = 0; mf < 4; mf++) {
#pragma unroll
        for (int nf = 0; nf < 4; nf++) {
            int row = ci * 128 + wm * 64 + mf * 16 + (lane >> 2);
            int col = cj * 128 + wn * 32 + nf * 8 + (lane & 3) * 2;
            atomicAdd(&g_S[row * 256 + col],       d[mf][nf][0]);
            atomicAdd(&g_S[row * 256 + col + 1],   d[mf][nf][1]);
            atomicAdd(&g_S[(row + 8) * 256 + col], d[mf][nf][2]);
            atomicAdd(&g_S[(row + 8) * 256 + col + 1], d[mf][nf][3]);
        }
    }
}

// ---------------- 4: T = Wk @ S (reads S with symmetric indexing) ----------------
__global__ void fixT_kernel(const float* __restrict__ Wk) {
    __shared__ float w[256];
    int i = blockIdx.x, j = threadIdx.x;
    w[j] = Wk[i * CC + j];
    __syncthreads();
    float acc = 0.f;
#pragma unroll 4
    for (int c = 0; c < 256; c++) {
        float s = (c >= 128 && j < 128) ? g_S[j * 256 + c] : g_S[c * 256 + j];
        acc += w[c] * s;
    }
    g_T[i * 256 + j] = acc;
}

// ---------------- 5: ksum / vsum ----------------
__global__ void sumvec_kernel(const float* __restrict__ Wk, const float* __restrict__ bk,
                              const float* __restrict__ Wv, const float* __restrict__ bv) {
    __shared__ float xs[256];
    int t = threadIdx.x;
    xs[t] = g_xsum[t];
    __syncthreads();
    const float* W = blockIdx.x ? Wv : Wk;
    const float* bb = blockIdx.x ? bv : bk;
    float* dst = blockIdx.x ? g_vsum : g_ksum;
    float acc = 0.f;
#pragma unroll 4
    for (int c = 0; c < 256; c++) acc += W[t * CC + c] * xs[c];
    dst[t] = acc + FNN * bb[t];
}

// ---------------- 6: kv fix (blocks 0-63) + ksumsq (blocks 64-127) ----------------
__global__ void fix2_kernel(const float* __restrict__ Wk, const float* __restrict__ bk,
                            const float* __restrict__ Wv, const float* __restrict__ bv) {
    int b = blockIdx.x, t = threadIdx.x;
    if (b < 64) {
        int o = b * 256 + t;           // 0..16383
        int h = o >> 12, rem = o & 4095;
        int dd = rem >> 6, m = rem & 63;
        int rk = h * 64 + m, rv = h * 64 + dd;
        float acc = 0.f;
#pragma unroll 4
        for (int c = 0; c < 256; c++) acc += g_T[rk * 256 + c] * Wv[rv * CC + c];
        float kx = g_ksum[rk] - FNN * bk[rk];
        float vx = g_vsum[rv] - FNN * bv[rv];
        g_kv[h * 4096 + dd * 64 + m] =
            acc + kx * bv[rv] + bk[rk] * vx + FNN * bk[rk] * bv[rv];
    } else {
        int p = b - 64;
        float acc = 0.f;
#pragma unroll
        for (int j = 0; j < 4; j++) {
            int idx = p * 1024 + j * 256 + t;
            acc += g_T[idx] * Wk[idx];
        }
#pragma unroll
        for (int off = 16; off > 0; off >>= 1) acc += __shfl_xor_sync(0xffffffffu, acc, off);
        __shared__ float r8[8];
        if ((t & 31) == 0) r8[t >> 5] = acc;
        __syncthreads();
        if (t == 0) {
            float s = 0.f;
#pragma unroll
            for (int j = 0; j < 8; j++) s += r8[j];
            if (p == 0) {
                float e = 0.f;
                for (int i = 0; i < 256; i++) {
                    float kx = g_ksum[i] - FNN * bk[i];
                    e += 2.f * bk[i] * kx + FNN * bk[i] * bk[i];
                }
                s += e;
            }
            atomicAdd(&g_scal[1], s);
        }
    }
}

// ---------------- graph: degree ----------------
__global__ void degree_kernel(const int* __restrict__ ei) {
    int e = blockIdx.x * 256 + threadIdx.x;
    if (e < EE) atomicAdd(&g_deg[ei[EE + e]], 1.0f);
}

// ---------------- graph: parallel exclusive scan ----------------
__global__ void scan1_kernel() {
    int b = blockIdx.x, t = threadIdx.x;
    int i = b * 256 + t;
    int v = (i < NN) ? (int)g_deg[i] : 0;
#pragma unroll
    for (int off = 16; off > 0; off >>= 1) v += __shfl_xor_sync(0xffffffffu, v, off);
    __shared__ int ws[8];
    if ((t & 31) == 0) ws[t >> 5] = v;
    __syncthreads();
    if (t == 0) {
        int s = 0;
#pragma unroll
        for (int j = 0; j < 8; j++) s += ws[j];
        g_part[b] = s;
    }
}

__global__ void scan2_kernel() {
    int t = threadIdx.x;
    int v = (t < 196) ? g_part[t] : 0;
    int lane = t & 31, w = t >> 5;
    int x = v;
#pragma unroll
    for (int off = 1; off < 32; off <<= 1) {
        int y = __shfl_up_sync(0xffffffffu, x, off);
        if (lane >= off) x += y;
    }
    __shared__ int ws[8];
    if (lane == 31) ws[w] = x;
    __syncthreads();
    if (t == 0) {
        int c = 0;
#pragma unroll
        for (int j = 0; j < 8; j++) { int tmp = ws[j]; ws[j] = c; c += tmp; }
    }
    __syncthreads();
    int incl = x + ws[w];
    if (t < 196) g_part[t] = incl - v;
    if (t == 0) g_offs[NN] = EE;
}

__global__ void scan3_kernel() {
    int b = blockIdx.x, t = threadIdx.x;
    int i = b * 256 + t;
    int v = (i < NN) ? (int)g_deg[i] : 0;
    int lane = t & 31, w = t >> 5;
    int x = v;
#pragma unroll
    for (int off = 1; off < 32; off <<= 1) {
        int y = __shfl_up_sync(0xffffffffu, x, off);
        if (lane >= off) x += y;
    }
    __shared__ int ws[8];
    if (lane == 31) ws[w] = x;
    __syncthreads();
    if (t == 0) {
        int c = 0;
#pragma unroll
        for (int j = 0; j < 8; j++) { int tmp = ws[j]; ws[j] = c; c += tmp; }
    }
    __syncthreads();
    int excl = (x - v) + ws[w] + g_part[b];
    if (i < NN) { g_offs[i] = excl; g_cursor[i] = excl; }
}

// ---------------- graph: scatter to CSR-by-destination ----------------
__global__ void scatter_kernel(const int* __restrict__ ei, const float* __restrict__ ew) {
    int e = blockIdx.x * 256 + threadIdx.x;
    if (e >= EE) return;
    int r = ei[e];
    int c = ei[EE + e];
    float dc = g_deg[c];
    float dr = g_deg[r];
    float w = ew[e];
    float val = (dr > 0.f) ? w * rsqrtf(dc * dr) : 0.f;
    int slot = atomicAdd(&g_cursor[c], 1);
    g_src[slot] = r;
    g_val[slot] = val;
}

// ---------------- 7: attention epilogue via tf32 MMA ----------------
#define QST 68

__global__ void __launch_bounds__(256)
attn_kernel(float* __restrict__ out) {
    extern __shared__ uint32_t sm[];
    uint32_t* sq  = sm;
    uint32_t* skv = sm + 128 * QST;
    float* sden = (float*)(skv + 64 * QST);
    float* sks  = sden + 128;
    float* svs  = sks + 64;

    int t = threadIdx.x;
    int lane = t & 31, warp = t >> 5;
    int wm = warp >> 1;
    int wn = warp & 1;
    int m0 = blockIdx.x * 128;
    float scal = rsqrtf(g_scal[0]) * rsqrtf(g_scal[1]);

    float facc[2][4][4];
#pragma unroll
    for (int i = 0; i < 2; i++)
#pragma unroll
        for (int j = 0; j < 4; j++)
#pragma unroll
            for (int c = 0; c < 4; c++) facc[i][j][c] = 0.f;

    for (int h = 0; h < HH; h++) {
        __syncthreads();
        {
            int r = t >> 4;
            int c = (t & 15) * 4;
#pragma unroll
            for (int p = 0; p < 8; p++) {
                int row = p * 16 + r;
                int n = m0 + row;
                float4 v = make_float4(0.f, 0.f, 0.f, 0.f);
                if (n < NN) v = *(const float4*)&g_q[(size_t)n * OC + h * 64 + c];
                uint4 u = make_uint4(f2tf32(v.x), f2tf32(v.y), f2tf32(v.z), f2tf32(v.w));
                *(uint4*)&sq[row * QST + c] = u;
            }
#pragma unroll
            for (int p = 0; p < 4; p++) {
                int row = p * 16 + r;
                float4 v = *(const float4*)&g_kv[h * 4096 + row * 64 + c];
                uint4 u = make_uint4(f2tf32(v.x), f2tf32(v.y), f2tf32(v.z), f2tf32(v.w));
                *(uint4*)&skv[row * QST + c] = u;
            }
            if (t < 64) { sks[t] = g_ksum[h * 64 + t]; svs[t] = g_vsum[h * 64 + t]; }
        }
        __syncthreads();
        {
            int r = t >> 1, p = t & 1;
            float s = 0.f;
#pragma unroll
            for (int m = 0; m < 32; m++)
                s += __uint_as_float(sq[r * QST + p * 32 + m]) * sks[p * 32 + m];
            s += __shfl_xor_sync(0xffffffffu, s, 1);
            if (p == 0) sden[r] = scal * s + FNN;
        }
        __syncthreads();

        float num[2][4][4];
#pragma unroll
        for (int i = 0; i < 2; i++)
#pragma unroll
            for (int j = 0; j < 4; j++)
#pragma unroll
                for (int c = 0; c < 4; c++) num[i][j][c] = 0.f;

#pragma unroll
        for (int kf = 0; kf < 8; kf++) {
            int ka = kf * 8 + (lane & 3);
            uint32_t a[2][4];
#pragma unroll
            for (int mf = 0; mf < 2; mf++) {
                int ra = wm * 32 + mf * 16 + (lane >> 2);
                a[mf][0] = sq[ra * QST + ka];
                a[mf][1] = sq[(ra + 8) * QST + ka];
                a[mf][2] = sq[ra * QST + ka + 4];
                a[mf][3] = sq[(ra + 8) * QST + ka + 4];
            }
#pragma unroll
            for (int nf = 0; nf < 4; nf++) {
                int rb = wn * 32 + nf * 8 + (lane >> 2);
                uint32_t b[2];
                b[0] = skv[rb * QST + ka];
                b[1] = skv[rb * QST + ka + 4];
#pragma unroll
                for (int mf = 0; mf < 2; mf++)
                    mma_tf32(num[mf][nf][0], num[mf][nf][1], num[mf][nf][2], num[mf][nf][3],
                             a[mf], b);
            }
        }
#pragma unroll
        for (int mf = 0; mf < 2; mf++) {
            int rl = wm * 32 + mf * 16 + (lane >> 2);
            float i0 = 1.f / sden[rl];
            float i1 = 1.f / sden[rl + 8];
#pragma unroll
            for (int nf = 0; nf < 4; nf++) {
                int col = wn * 32 + nf * 8 + (lane & 3) * 2;
                float s0 = svs[col], s1 = svs[col + 1];
                facc[mf][nf][0] += (scal * num[mf][nf][0] + s0) * i0;
                facc[mf][nf][1] += (scal * num[mf][nf][1] + s1) * i0;
                facc[mf][nf][2] += (scal * num[mf][nf][2] + s0) * i1;
                facc[mf][nf][3] += (scal * num[mf][nf][3] + s1) * i1;
            }
        }
    }
#pragma unroll
    for (int mf = 0; mf < 2; mf++) {
#pragma unroll
        for (int nf = 0; nf < 4; nf++) {
            int row = m0 + wm * 32 + mf * 16 + (lane >> 2);
            int col = wn * 32 + nf * 8 + (lane & 3) * 2;
            if (row < NN)
                *(float2*)&out[(size_t)row * 64 + col] =
                    make_float2(0.25f * facc[mf][nf][0], 0.25f * facc[mf][nf][1]);
            if (row + 8 < NN)
                *(float2*)&out[(size_t)(row + 8) * 64 + col] =
                    make_float2(0.25f * facc[mf][nf][2], 0.25f * facc[mf][nf][3]);
        }
    }
}

// ---------------- 8: GCN gather (atomic-free), out += sum ----------------
__global__ void gather_kernel(float* __restrict__ out) {
    int t = threadIdx.x;
    int n = blockIdx.x * 4 + (t >> 6);
    int dd = t & 63;
    if (n >= NN) return;
    int e0 = g_offs[n], e1 = g_offs[n + 1];
    float acc = 0.f;
    for (int e = e0; e < e1; ++e) {
        int r = g_src[e];
        float val = g_val[e];
        acc += val * g_vbar[(size_t)r * 64 + dd];
    }
    out[(size_t)n * 64 + dd] += acc;
}

// ---------------- launch ----------------
extern "C" void kernel_launch(void* const* d_in, const int* in_sizes, int n_in,
                              void* d_out, int out_size) {
    const float* query = (const float*)d_in[0];
    const float* source = (const float*)d_in[1];
    const float* Wq = (const float*)d_in[2];
    const float* bq = (const float*)d_in[3];
    const float* Wk = (const float*)d_in[4];
    const float* bk = (const float*)d_in[5];
    const float* Wv = (const float*)d_in[6];
    const float* bv = (const float*)d_in[7];
    const int*   ei = (const int*)d_in[8];
    const float* ew = (const float*)d_in[9];
    float* out = (float*)d_out;

    const int gemmq_smem = 4 * TSZ * (int)sizeof(float);                    // 73728
    const int vbar_smem  = (2 * TSZ + 2 * 64 * AST) * (int)sizeof(float);   // 55296
    const int syrk_smem  = 4 * 32 * SST * (int)sizeof(float);               // 67584
    const int attn_smem  = (128 * QST + 64 * QST) * 4 + (128 + 64 + 64) * 4;

    cudaFuncSetAttribute(gemm_q,      cudaFuncAttributeMaxDynamicSharedMemorySize, gemmq_smem);
    cudaFuncSetAttribute(gemm_vbar,   cudaFuncAttributeMaxDynamicSharedMemorySize, vbar_smem);
    cudaFuncSetAttribute(syrk_kernel, cudaFuncAttributeMaxDynamicSharedMemorySize, syrk_smem);
    cudaFuncSetAttribute(attn_kernel, cudaFuncAttributeMaxDynamicSharedMemorySize, attn_smem);

    zero_kernel<<<256, 256>>>(Wv, bv);
    gemm_q<<<dim3(2, 391), 256, gemmq_smem>>>(query, Wq, bq);
    gemm_vbar<<<391, 256, vbar_smem>>>(source);
    syrk_kernel<<<dim3(NCH, 3), 256, syrk_smem>>>(source);
    fixT_kernel<<<256, 256>>>(Wk);
    sumvec_kernel<<<2, 256>>>(Wk, bk, Wv, bv);
    fix2_kernel<<<128, 256>>>(Wk, bk, Wv, bv);
    degree_kernel<<<(EE + 255) / 256, 256>>>(ei);
    scan1_kernel<<<196, 256>>>();
    scan2_kernel<<<1, 256>>>();
    scan3_kernel<<<196, 256>>>();
    scatter_kernel<<<(EE + 255) / 256, 256>>>(ei, ew);
    attn_kernel<<<391, 256, attn_smem>>>(out);
    gather_kernel<<<(NN + 3) / 4, 256>>>(out);
}

// round 8
// speedup vs baseline: 7.7685x; 1.2582x over previous
#include <cuda_runtime.h>
#include <cuda_bf16.h>
#include <math.h>
#include <stdint.h>

#define NN 50000
#define CC 256
#define HH 4
#define DD 64
#define EE 800000
#define OC 256   // H*D
#define FNN 50000.0f

// ---------------- device scratch ----------------
__device__ float g_q[NN * OC];
__device__ float g_vbar[NN * DD];
__device__ float g_S[OC * OC];       // Xs^T Xs
__device__ float g_T[OC * OC];       // Wk @ S
__device__ float g_xsum[OC];
__device__ float g_wvbar[DD * CC];
__device__ float g_bvbar[DD];
__device__ float g_ksum[OC];
__device__ float g_vsum[OC];
__device__ float g_kv[HH * DD * DD]; // [h][d][m]
__device__ float g_scal[2];
__device__ float g_deg[NN];
__device__ int   g_offs[NN + 1];
__device__ int   g_cursor[NN];
__device__ int   g_src[EE];
__device__ float g_val[EE];
__device__ int   g_part[256];

// ---------------- helpers ----------------
__device__ __forceinline__ uint32_t f2tf32(float x) {
    uint32_t r;
    asm("cvt.rna.tf32.f32 %0, %1;" : "=r"(r) : "f"(x));
    return r;
}
__device__ __forceinline__ uint32_t pk(float lo, float hi) {
    uint32_t r;
    asm("cvt.rn.bf16x2.f32 %0, %1, %2;" : "=r"(r) : "f"(hi), "f"(lo));
    return r;
}
__device__ __forceinline__ void mma_tf32(float& d0, float& d1, float& d2, float& d3,
                                         const uint32_t* a, const uint32_t* b) {
    asm volatile(
        "mma.sync.aligned.m16n8k8.row.col.f32.tf32.tf32.f32 "
        "{%0,%1,%2,%3}, {%4,%5,%6,%7}, {%8,%9}, {%0,%1,%2,%3};\n"
        : "+f"(d0), "+f"(d1), "+f"(d2), "+f"(d3)
        : "r"(a[0]), "r"(a[1]), "r"(a[2]), "r"(a[3]), "r"(b[0]), "r"(b[1]));
}
__device__ __forceinline__ void mma_bf16(float& d0, float& d1, float& d2, float& d3,
                                         const uint32_t* a, const uint32_t* b) {
    asm volatile(
        "mma.sync.aligned.m16n8k16.row.col.f32.bf16.bf16.f32 "
        "{%0,%1,%2,%3}, {%4,%5,%6,%7}, {%8,%9}, {%0,%1,%2,%3};\n"
        : "+f"(d0), "+f"(d1), "+f"(d2), "+f"(d3)
        : "r"(a[0]), "r"(a[1]), "r"(a[2]), "r"(a[3]), "r"(b[0]), "r"(b[1]));
}

// ---------------- L1: zero scratch + Wvbar prep ----------------
__global__ void zero_kernel(const float* __restrict__ Wv, const float* __restrict__ bv) {
    int i = blockIdx.x * 256 + threadIdx.x;   // 65536
    g_S[i] = 0.f;
    if (i < NN) g_deg[i] = 0.f;
    if (i < OC) g_xsum[i] = 0.f;
    if (i < 2) g_scal[i] = 0.f;
    if (i < DD * CC) {
        int d = i >> 8, c = i & 255;
        g_wvbar[i] = 0.25f * (Wv[(d) * CC + c] + Wv[(d + 64) * CC + c] +
                              Wv[(d + 128) * CC + c] + Wv[(d + 192) * CC + c]);
    }
    if (i < DD)
        g_bvbar[i] = 0.25f * (bv[i] + bv[i + 64] + bv[i + 128] + bv[i + 192]);
}

// ======================== phase1 bodies ========================
#define BK 32
#define AST 36
#define TSZ (128 * AST)
#define SST 132
#define CHK 1024
#define NCH 49

// ---- SYRK tile body ----
__device__ void syrk_body(float* smf, int bidx, const float* __restrict__ Xs) {
    float* Ai = smf;
    float* Bj = smf + 2 * 32 * SST;
    int t = threadIdx.x;
    int tile = bidx / NCH;            // 0:(0,0) 1:(0,1) 2:(1,1)
    int chunk = bidx % NCH;
    int ci = (tile == 2) ? 1 : 0;
    int cj = (tile == 0) ? 0 : 1;
    int diag = (ci == cj);
    int nbase = chunk * CHK;
    int lane = t & 31, warp = t >> 5;
    int wm = warp & 1, wn = warp >> 1;

    auto load_tile = [&](int stage, int s) {
#pragma unroll
        for (int p = 0; p < 4; p++) {
            int idx = p * 256 + t;
            int r = idx >> 5;
            int c4 = (idx & 31) * 4;
            int node = nbase + s + r;
            int ok = (node < NN);
            const float* srcA = Xs + (size_t)(ok ? node : 0) * CC + ci * 128 + c4;
            uint32_t da = (uint32_t)__cvta_generic_to_shared(&Ai[stage * 32 * SST + r * SST + c4]);
            int sz = ok ? 16 : 0;
            asm volatile("cp.async.cg.shared.global [%0], [%1], 16, %2;\n"
                         :: "r"(da), "l"(srcA), "r"(sz));
            if (!diag) {
                const float* srcB = Xs + (size_t)(ok ? node : 0) * CC + cj * 128 + c4;
                uint32_t db = (uint32_t)__cvta_generic_to_shared(&Bj[stage * 32 * SST + r * SST + c4]);
                asm volatile("cp.async.cg.shared.global [%0], [%1], 16, %2;\n"
                             :: "r"(db), "l"(srcB), "r"(sz));
            }
        }
        asm volatile("cp.async.commit_group;\n");
    };

    float d[4][4][4];
#pragma unroll
    for (int i = 0; i < 4; i++)
#pragma unroll
        for (int j = 0; j < 4; j++)
#pragma unroll
            for (int c = 0; c < 4; c++) d[i][j][c] = 0.f;

    load_tile(0, 0);
    for (int si = 0; si < CHK / 32; si++) {
        if (si < CHK / 32 - 1) {
            load_tile((si + 1) & 1, (si + 1) * 32);
            asm volatile("cp.async.wait_group 1;\n");
        } else {
            asm volatile("cp.async.wait_group 0;\n");
        }
        __syncthreads();
        const float* Af = Ai + (si & 1) * 32 * SST;
        const float* Bf = diag ? Af : (Bj + (si & 1) * 32 * SST);
#pragma unroll
        for (int kf = 0; kf < 2; kf++) {
            int k = kf * 16 + (lane & 3) * 2;
            uint32_t a[4][4], b[4][2];
#pragma unroll
            for (int mf = 0; mf < 4; mf++) {
                int ra = wm * 64 + mf * 16 + (lane >> 2);
                a[mf][0] = pk(Af[k * SST + ra],       Af[(k + 1) * SST + ra]);
                a[mf][1] = pk(Af[k * SST + ra + 8],   Af[(k + 1) * SST + ra + 8]);
                a[mf][2] = pk(Af[(k + 8) * SST + ra], Af[(k + 9) * SST + ra]);
                a[mf][3] = pk(Af[(k + 8) * SST + ra + 8], Af[(k + 9) * SST + ra + 8]);
            }
#pragma unroll
            for (int nf = 0; nf < 4; nf++) {
                int rb = wn * 32 + nf * 8 + (lane >> 2);
                b[nf][0] = pk(Bf[k * SST + rb],       Bf[(k + 1) * SST + rb]);
                b[nf][1] = pk(Bf[(k + 8) * SST + rb], Bf[(k + 9) * SST + rb]);
            }
#pragma unroll
            for (int nf = 0; nf < 4; nf++)
#pragma unroll
                for (int mf = 0; mf < 4; mf++)
                    mma_bf16(d[mf][nf][0], d[mf][nf][1], d[mf][nf][2], d[mf][nf][3],
                             a[mf], b[nf]);
        }
        __syncthreads();
    }
#pragma unroll
    for (int mf = 0; mf < 4; mf++) {
#pragma unroll
        for (int nf = 0; nf < 4; nf++) {
            int row = ci * 128 + wm * 64 + mf * 16 + (lane >> 2);
            int col = cj * 128 + wn * 32 + nf * 8 + (lane & 3) * 2;
            atomicAdd(&g_S[row * 256 + col],       d[mf][nf][0]);
            atomicAdd(&g_S[row * 256 + col + 1],   d[mf][nf][1]);
            atomicAdd(&g_S[(row + 8) * 256 + col], d[mf][nf][2]);
            atomicAdd(&g_S[(row + 8) * 256 + col + 1], d[mf][nf][3]);
        }
    }
}

// ---- Q GEMM body (bf16) ----
__device__ void gemmq_body(float* smf, int bi, const float* __restrict__ X,
                           const float* __restrict__ W, const float* __restrict__ B) {
    float* As = smf;
    float* Bs = smf + 2 * TSZ;
    __shared__ float red8[8];

    int t = threadIdx.x;
    int m0 = (bi >> 1) * 128;
    int n0 = (bi & 1) * 128;
    int lane = t & 31, warp = t >> 5;
    int wm = warp & 1, wn = warp >> 1;
    int lr = t >> 3, lc = (t & 7) * 4;

    auto load_tile = [&](int stage, int k0) {
#pragma unroll
        for (int p = 0; p < 4; p++) {
            int r = p * 32 + lr;
            int gr = m0 + r;
            int ok = (gr < NN);
            const float* srcA = X + (size_t)(ok ? gr : 0) * CC + k0 + lc;
            uint32_t da = (uint32_t)__cvta_generic_to_shared(&As[stage * TSZ + r * AST + lc]);
            int szA = ok ? 16 : 0;
            asm volatile("cp.async.cg.shared.global [%0], [%1], 16, %2;\n"
                         :: "r"(da), "l"(srcA), "r"(szA));
            const float* srcB = W + (size_t)(n0 + r) * CC + k0 + lc;
            uint32_t db = (uint32_t)__cvta_generic_to_shared(&Bs[stage * TSZ + r * AST + lc]);
            asm volatile("cp.async.cg.shared.global [%0], [%1], 16;\n"
                         :: "r"(db), "l"(srcB));
        }
        asm volatile("cp.async.commit_group;\n");
    };

    float d[4][4][4];
#pragma unroll
    for (int i = 0; i < 4; i++)
#pragma unroll
        for (int j = 0; j < 4; j++)
#pragma unroll
            for (int c = 0; c < 4; c++) d[i][j][c] = 0.f;

    load_tile(0, 0);
    for (int ki = 0; ki < CC / BK; ki++) {
        if (ki < CC / BK - 1) {
            load_tile((ki + 1) & 1, (ki + 1) * BK);
            asm volatile("cp.async.wait_group 1;\n");
        } else {
            asm volatile("cp.async.wait_group 0;\n");
        }
        __syncthreads();
        const float* Af = As + (ki & 1) * TSZ;
        const float* Bf = Bs + (ki & 1) * TSZ;
#pragma unroll
        for (int kf = 0; kf < 2; kf++) {
            int ka = kf * 16 + (lane & 3) * 2;
            uint32_t a[4][4], b[4][2];
#pragma unroll
            for (int mf = 0; mf < 4; mf++) {
                int ra = wm * 64 + mf * 16 + (lane >> 2);
                float2 x0 = *(const float2*)&Af[ra * AST + ka];
                float2 x1 = *(const float2*)&Af[(ra + 8) * AST + ka];
                float2 x2 = *(const float2*)&Af[ra * AST + ka + 8];
                float2 x3 = *(const float2*)&Af[(ra + 8) * AST + ka + 8];
                a[mf][0] = pk(x0.x, x0.y); a[mf][1] = pk(x1.x, x1.y);
                a[mf][2] = pk(x2.x, x2.y); a[mf][3] = pk(x3.x, x3.y);
            }
#pragma unroll
            for (int nf = 0; nf < 4; nf++) {
                int rb = wn * 32 + nf * 8 + (lane >> 2);
                float2 y0 = *(const float2*)&Bf[rb * AST + ka];
                float2 y1 = *(const float2*)&Bf[rb * AST + ka + 8];
                b[nf][0] = pk(y0.x, y0.y); b[nf][1] = pk(y1.x, y1.y);
            }
#pragma unroll
            for (int nf = 0; nf < 4; nf++)
#pragma unroll
                for (int mf = 0; mf < 4; mf++)
                    mma_bf16(d[mf][nf][0], d[mf][nf][1], d[mf][nf][2], d[mf][nf][3],
                             a[mf], b[nf]);
        }
        __syncthreads();
    }

    float qs = 0.f;
#pragma unroll
    for (int mf = 0; mf < 4; mf++) {
#pragma unroll
        for (int nf = 0; nf < 4; nf++) {
            int row = m0 + wm * 64 + mf * 16 + (lane >> 2);
            int col = n0 + wn * 32 + nf * 8 + (lane & 3) * 2;
            float bi0 = B[col], bi1 = B[col + 1];
            if (row < NN) {
                float o0 = d[mf][nf][0] + bi0, o1 = d[mf][nf][1] + bi1;
                *(float2*)&g_q[(size_t)row * OC + col] = make_float2(o0, o1);
                qs += o0 * o0 + o1 * o1;
            }
            if (row + 8 < NN) {
                float o0 = d[mf][nf][2] + bi0, o1 = d[mf][nf][3] + bi1;
                *(float2*)&g_q[(size_t)(row + 8) * OC + col] = make_float2(o0, o1);
                qs += o0 * o0 + o1 * o1;
            }
        }
    }
#pragma unroll
    for (int off = 16; off > 0; off >>= 1) qs += __shfl_xor_sync(0xffffffffu, qs, off);
    if (lane == 0) red8[warp] = qs;
    __syncthreads();
    if (t == 0) {
        float s = 0.f;
#pragma unroll
        for (int j = 0; j < 8; j++) s += red8[j];
        atomicAdd(&g_scal[0], s);
    }
}

// ---- vbar GEMM body (tf32) + xsum fold ----
__device__ void vbar_body(float* smf, int bi, const float* __restrict__ Xs) {
    float* As = smf;
    float* Bs = smf + 2 * TSZ;

    int t = threadIdx.x;
    int m0 = bi * 128;
    int lane = t & 31, warp = t >> 5;
    int lr = t >> 3, lc = (t & 7) * 4;

    auto load_tile = [&](int stage, int k0) {
#pragma unroll
        for (int p = 0; p < 4; p++) {
            int r = p * 32 + lr;
            int gr = m0 + r;
            int ok = (gr < NN);
            const float* srcA = Xs + (size_t)(ok ? gr : 0) * CC + k0 + lc;
            uint32_t da = (uint32_t)__cvta_generic_to_shared(&As[stage * TSZ + r * AST + lc]);
            int szA = ok ? 16 : 0;
            asm volatile("cp.async.cg.shared.global [%0], [%1], 16, %2;\n"
                         :: "r"(da), "l"(srcA), "r"(szA));
        }
#pragma unroll
        for (int p = 0; p < 2; p++) {
            int r = p * 32 + lr;
            const float* srcB = g_wvbar + (size_t)r * CC + k0 + lc;
            uint32_t db = (uint32_t)__cvta_generic_to_shared(&Bs[stage * 64 * AST + r * AST + lc]);
            asm volatile("cp.async.cg.shared.global [%0], [%1], 16;\n"
                         :: "r"(db), "l"(srcB));
        }
        asm volatile("cp.async.commit_group;\n");
    };

    float acc[8][4];
#pragma unroll
    for (int i = 0; i < 8; i++)
#pragma unroll
        for (int c = 0; c < 4; c++) acc[i][c] = 0.f;

    load_tile(0, 0);
    for (int ki = 0; ki < CC / BK; ki++) {
        if (ki < CC / BK - 1) {
            load_tile((ki + 1) & 1, (ki + 1) * BK);
            asm volatile("cp.async.wait_group 1;\n");
        } else {
            asm volatile("cp.async.wait_group 0;\n");
        }
        __syncthreads();
        const float* Af = As + (ki & 1) * TSZ;
        const float* Bf = Bs + (ki & 1) * 64 * AST;
        {
            int col = t & 31, rg = t >> 5;
            float p = 0.f;
#pragma unroll
            for (int r = 0; r < 16; r++) p += Af[(rg * 16 + r) * AST + col];
            atomicAdd(&g_xsum[ki * 32 + col], p);
        }
#pragma unroll
        for (int kf = 0; kf < 4; kf++) {
            int ka = kf * 8 + (lane & 3);
            uint32_t a[4];
            int ra = warp * 16 + (lane >> 2);
            a[0] = f2tf32(Af[ra * AST + ka]);
            a[1] = f2tf32(Af[(ra + 8) * AST + ka]);
            a[2] = f2tf32(Af[ra * AST + ka + 4]);
            a[3] = f2tf32(Af[(ra + 8) * AST + ka + 4]);
#pragma unroll
            for (int nf = 0; nf < 8; nf++) {
                int rb = nf * 8 + (lane >> 2);
                uint32_t b[2];
                b[0] = f2tf32(Bf[rb * AST + ka]);
                b[1] = f2tf32(Bf[rb * AST + ka + 4]);
                mma_tf32(acc[nf][0], acc[nf][1], acc[nf][2], acc[nf][3], a, b);
            }
        }
        __syncthreads();
    }
#pragma unroll
    for (int nf = 0; nf < 8; nf++) {
        int row = m0 + warp * 16 + (lane >> 2);
        int col = nf * 8 + (lane & 3) * 2;
        float b0 = g_bvbar[col], b1 = g_bvbar[col + 1];
        if (row < NN)
            *(float2*)&g_vbar[(size_t)row * DD + col] =
                make_float2(acc[nf][0] + b0, acc[nf][1] + b1);
        if (row + 8 < NN)
            *(float2*)&g_vbar[(size_t)(row + 8) * DD + col] =
                make_float2(acc[nf][2] + b0, acc[nf][3] + b1);
    }
}

// ---- phase1 dispatcher: syrk(147) | gemm_q(782) | vbar(391) | degree(391) ----
#define P1_SYRK 147
#define P1_GEMM (P1_SYRK + 782)   // 929
#define P1_VBAR (P1_GEMM + 391)   // 1320
#define P1_TOTAL (P1_VBAR + 391)  // 1711

__global__ void __launch_bounds__(256, 2)
phase1(const float* __restrict__ Xq, const float* __restrict__ Wq, const float* __restrict__ bq,
       const float* __restrict__ Xs, const int* __restrict__ ei)
{
    extern __shared__ float smf[];
    int b = blockIdx.x;
    if (b < P1_SYRK) {
        syrk_body(smf, b, Xs);
    } else if (b < P1_GEMM) {
        gemmq_body(smf, b - P1_SYRK, Xq, Wq, bq);
    } else if (b < P1_VBAR) {
        vbar_body(smf, b - P1_GEMM, Xs);
    } else {
        int gs = b - P1_VBAR;
        for (int e = gs * 256 + threadIdx.x; e < EE; e += 391 * 256)
            atomicAdd(&g_deg[ei[EE + e]], 1.0f);
    }
}

// ======================== phase2: fixT(256) | scan1(196) | sumvec(2) ========================
__global__ void phase2(const float* __restrict__ Wk, const float* __restrict__ bk,
                       const float* __restrict__ Wv, const float* __restrict__ bv)
{
    int b = blockIdx.x, t = threadIdx.x;
    if (b < 256) {
        __shared__ float w[256];
        w[t] = Wk[b * CC + t];
        __syncthreads();
        float acc = 0.f;
#pragma unroll 4
        for (int c = 0; c < 256; c++) {
            float s = (c >= 128 && t < 128) ? g_S[t * 256 + c] : g_S[c * 256 + t];
            acc += w[c] * s;
        }
        g_T[b * 256 + t] = acc;
    } else if (b < 452) {
        int blk = b - 256;
        int i = blk * 256 + t;
        int v = (i < NN) ? (int)g_deg[i] : 0;
#pragma unroll
        for (int off = 16; off > 0; off >>= 1) v += __shfl_xor_sync(0xffffffffu, v, off);
        __shared__ int ws[8];
        if ((t & 31) == 0) ws[t >> 5] = v;
        __syncthreads();
        if (t == 0) {
            int s = 0;
#pragma unroll
            for (int j = 0; j < 8; j++) s += ws[j];
            g_part[blk] = s;
        }
    } else {
        int sel = b - 452;
        __shared__ float xs[256];
        xs[t] = g_xsum[t];
        __syncthreads();
        const float* W = sel ? Wv : Wk;
        const float* bb = sel ? bv : bk;
        float* dst = sel ? g_vsum : g_ksum;
        float acc = 0.f;
#pragma unroll 4
        for (int c = 0; c < 256; c++) acc += W[t * CC + c] * xs[c];
        dst[t] = acc + FNN * bb[t];
    }
}

// ======================== phase3: fix2(128) | scan2(1) ========================
__global__ void phase3(const float* __restrict__ Wk, const float* __restrict__ bk,
                       const float* __restrict__ Wv, const float* __restrict__ bv)
{
    int b = blockIdx.x, t = threadIdx.x;
    if (b < 64) {
        int o = b * 256 + t;
        int h = o >> 12, rem = o & 4095;
        int dd = rem >> 6, m = rem & 63;
        int rk = h * 64 + m, rv = h * 64 + dd;
        float acc = 0.f;
#pragma unroll 4
        for (int c = 0; c < 256; c++) acc += g_T[rk * 256 + c] * Wv[rv * CC + c];
        float kx = g_ksum[rk] - FNN * bk[rk];
        float vx = g_vsum[rv] - FNN * bv[rv];
        g_kv[h * 4096 + dd * 64 + m] =
            acc + kx * bv[rv] + bk[rk] * vx + FNN * bk[rk] * bv[rv];
    } else if (b < 128) {
        int p = b - 64;
        float acc = 0.f;
#pragma unroll
        for (int j = 0; j < 4; j++) {
            int idx = p * 1024 + j * 256 + t;
            acc += g_T[idx] * Wk[idx];
        }
#pragma unroll
        for (int off = 16; off > 0; off >>= 1) acc += __shfl_xor_sync(0xffffffffu, acc, off);
        __shared__ float r8[8];
        if ((t & 31) == 0) r8[t >> 5] = acc;
        __syncthreads();
        if (t == 0) {
            float s = 0.f;
#pragma unroll
            for (int j = 0; j < 8; j++) s += r8[j];
            if (p == 0) {
                float e = 0.f;
                for (int i = 0; i < 256; i++) {
                    float kx = g_ksum[i] - FNN * bk[i];
                    e += 2.f * bk[i] * kx + FNN * bk[i] * bk[i];
                }
                s += e;
            }
            atomicAdd(&g_scal[1], s);
        }
    } else {
        // scan2: exclusive scan of 196 block partials
        int v = (t < 196) ? g_part[t] : 0;
        int lane = t & 31, w = t >> 5;
        int x = v;
#pragma unroll
        for (int off = 1; off < 32; off <<= 1) {
            int y = __shfl_up_sync(0xffffffffu, x, off);
            if (lane >= off) x += y;
        }
        __shared__ int ws[8];
        if (lane == 31) ws[w] = x;
        __syncthreads();
        if (t == 0) {
            int c = 0;
#pragma unroll
            for (int j = 0; j < 8; j++) { int tmp = ws[j]; ws[j] = c; c += tmp; }
        }
        __syncthreads();
        int incl = x + ws[w];
        if (t < 196) g_part[t] = incl - v;
        if (t == 0) g_offs[NN] = EE;
    }
}

// ======================== phase4: scan3 (196) ========================
__global__ void phase4() {
    int b = blockIdx.x, t = threadIdx.x;
    int i = b * 256 + t;
    int v = (i < NN) ? (int)g_deg[i] : 0;
    int lane = t & 31, w = t >> 5;
    int x = v;
#pragma unroll
    for (int off = 1; off < 32; off <<= 1) {
        int y = __shfl_up_sync(0xffffffffu, x, off);
        if (lane >= off) x += y;
    }
    __shared__ int ws[8];
    if (lane == 31) ws[w] = x;
    __syncthreads();
    if (t == 0) {
        int c = 0;
#pragma unroll
        for (int j = 0; j < 8; j++) { int tmp = ws[j]; ws[j] = c; c += tmp; }
    }
    __syncthreads();
    int excl = (x - v) + ws[w] + g_part[b];
    if (i < NN) { g_offs[i] = excl; g_cursor[i] = excl; }
}

// ======================== phase5: attn(391) | scatter(784 grid-stride) ========================
#define QST 68
#define P5_ATTN 391
#define P5_TOTAL (P5_ATTN + 784)

__device__ void attn_body(uint32_t* sm, int bi, float* __restrict__ out) {
    uint32_t* sq  = sm;
    uint32_t* skv = sm + 128 * QST;
    float* sden = (float*)(skv + 64 * QST);
    float* sks  = sden + 128;
    float* svs  = sks + 64;

    int t = threadIdx.x;
    int lane = t & 31, warp = t >> 5;
    int wm = warp >> 1;
    int wn = warp & 1;
    int m0 = bi * 128;
    float scal = rsqrtf(g_scal[0]) * rsqrtf(g_scal[1]);

    float facc[2][4][4];
#pragma unroll
    for (int i = 0; i < 2; i++)
#pragma unroll
        for (int j = 0; j < 4; j++)
#pragma unroll
            for (int c = 0; c < 4; c++) facc[i][j][c] = 0.f;

    for (int h = 0; h < HH; h++) {
        __syncthreads();
        {
            int r = t >> 4;
            int c = (t & 15) * 4;
#pragma unroll
            for (int p = 0; p < 8; p++) {
                int row = p * 16 + r;
                int n = m0 + row;
                float4 v = make_float4(0.f, 0.f, 0.f, 0.f);
                if (n < NN) v = *(const float4*)&g_q[(size_t)n * OC + h * 64 + c];
                uint4 u = make_uint4(f2tf32(v.x), f2tf32(v.y), f2tf32(v.z), f2tf32(v.w));
                *(uint4*)&sq[row * QST + c] = u;
            }
#pragma unroll
            for (int p = 0; p < 4; p++) {
                int row = p * 16 + r;
                float4 v = *(const float4*)&g_kv[h * 4096 + row * 64 + c];
                uint4 u = make_uint4(f2tf32(v.x), f2tf32(v.y), f2tf32(v.z), f2tf32(v.w));
                *(uint4*)&skv[row * QST + c] = u;
            }
            if (t < 64) { sks[t] = g_ksum[h * 64 + t]; svs[t] = g_vsum[h * 64 + t]; }
        }
        __syncthreads();
        {
            int r = t >> 1, p = t & 1;
            float s = 0.f;
#pragma unroll
            for (int m = 0; m < 32; m++)
                s += __uint_as_float(sq[r * QST + p * 32 + m]) * sks[p * 32 + m];
            s += __shfl_xor_sync(0xffffffffu, s, 1);
            if (p == 0) sden[r] = scal * s + FNN;
        }
        __syncthreads();

        float num[2][4][4];
#pragma unroll
        for (int i = 0; i < 2; i++)
#pragma unroll
            for (int j = 0; j < 4; j++)
#pragma unroll
                for (int c = 0; c < 4; c++) num[i][j][c] = 0.f;

#pragma unroll
        for (int kf = 0; kf < 8; kf++) {
            int ka = kf * 8 + (lane & 3);
            uint32_t a[2][4];
#pragma unroll
            for (int mf = 0; mf < 2; mf++) {
                int ra = wm * 32 + mf * 16 + (lane >> 2);
                a[mf][0] = sq[ra * QST + ka];
                a[mf][1] = sq[(ra + 8) * QST + ka];
                a[mf][2] = sq[ra * QST + ka + 4];
                a[mf][3] = sq[(ra + 8) * QST + ka + 4];
            }
#pragma unroll
            for (int nf = 0; nf < 4; nf++) {
                int rb = wn * 32 + nf * 8 + (lane >> 2);
                uint32_t b[2];
                b[0] = skv[rb * QST + ka];
                b[1] = skv[rb * QST + ka + 4];
#pragma unroll
                for (int mf = 0; mf < 2; mf++)
                    mma_tf32(num[mf][nf][0], num[mf][nf][1], num[mf][nf][2], num[mf][nf][3],
                             a[mf], b);
            }
        }
#pragma unroll
        for (int mf = 0; mf < 2; mf++) {
            int rl = wm * 32 + mf * 16 + (lane >> 2);
            float i0 = 1.f / sden[rl];
            float i1 = 1.f / sden[rl + 8];
#pragma unroll
            for (int nf = 0; nf < 4; nf++) {
                int col = wn * 32 + nf * 8 + (lane & 3) * 2;
                float s0 = svs[col], s1 = svs[col + 1];
                facc[mf][nf][0] += (scal * num[mf][nf][0] + s0) * i0;
                facc[mf][nf][1] += (scal * num[mf][nf][1] + s1) * i0;
                facc[mf][nf][2] += (scal * num[mf][nf][2] + s0) * i1;
                facc[mf][nf][3] += (scal * num[mf][nf][3] + s1) * i1;
            }
        }
    }
#pragma unroll
    for (int mf = 0; mf < 2; mf++) {
#pragma unroll
        for (int nf = 0; nf < 4; nf++) {
            int row = m0 + wm * 32 + mf * 16 + (lane >> 2);
            int col = wn * 32 + nf * 8 + (lane & 3) * 2;
            if (row < NN)
                *(float2*)&out[(size_t)row * 64 + col] =
                    make_float2(0.25f * facc[mf][nf][0], 0.25f * facc[mf][nf][1]);
            if (row + 8 < NN)
                *(float2*)&out[(size_t)(row + 8) * 64 + col] =
                    make_float2(0.25f * facc[mf][nf][2], 0.25f * facc[mf][nf][3]);
        }
    }
}

__global__ void __launch_bounds__(256)
phase5(float* __restrict__ out, const int* __restrict__ ei, const float* __restrict__ ew) {
    extern __shared__ uint32_t smu[];
    int b = blockIdx.x;
    if (b < P5_ATTN) {
        attn_body(smu, b, out);
    } else {
        int gs = b - P5_ATTN;
        for (int e = gs * 256 + threadIdx.x; e < EE; e += 784 * 256) {
            int r = ei[e];
            int c = ei[EE + e];
            float dc = g_deg[c];
            float dr = g_deg[r];
            float w = ew[e];
            float val = (dr > 0.f) ? w * rsqrtf(dc * dr) : 0.f;
            int slot = atomicAdd(&g_cursor[c], 1);
            g_src[slot] = r;
            g_val[slot] = val;
        }
    }
}

// ======================== phase6: GCN gather (atomic-free) ========================
__global__ void phase6(float* __restrict__ out) {
    int t = threadIdx.x;
    int n = blockIdx.x * 4 + (t >> 6);
    int dd = t & 63;
    if (n >= NN) return;
    int e0 = g_offs[n], e1 = g_offs[n + 1];
    float acc = 0.f;
    for (int e = e0; e < e1; ++e) {
        int r = g_src[e];
        float val = g_val[e];
        acc += val * g_vbar[(size_t)r * 64 + dd];
    }
    out[(size_t)n * 64 + dd] += acc;
}

// ---------------- launch ----------------
extern "C" void kernel_launch(void* const* d_in, const int* in_sizes, int n_in,
                              void* d_out, int out_size) {
    const float* query = (const float*)d_in[0];
    const float* source = (const float*)d_in[1];
    const float* Wq = (const float*)d_in[2];
    const float* bq = (const float*)d_in[3];
    const float* Wk = (const float*)d_in[4];
    const float* bk = (const float*)d_in[5];
    const float* Wv = (const float*)d_in[6];
    const float* bv = (const float*)d_in[7];
    const int*   ei = (const int*)d_in[8];
    const float* ew = (const float*)d_in[9];
    float* out = (float*)d_out;

    const int p1_smem = 4 * TSZ * (int)sizeof(float);                       // 73728
    const int p5_smem = (128 * QST + 64 * QST) * 4 + (128 + 64 + 64) * 4;   // 53248

    cudaFuncSetAttribute(phase1, cudaFuncAttributeMaxDynamicSharedMemorySize, p1_smem);
    cudaFuncSetAttribute(phase5, cudaFuncAttributeMaxDynamicSharedMemorySize, p5_smem);

    zero_kernel<<<256, 256>>>(Wv, bv);
    phase1<<<P1_TOTAL, 256, p1_smem>>>(query, Wq, bq, source, ei);
    phase2<<<454, 256>>>(Wk, bk, Wv, bv);
    phase3<<<129, 256>>>(Wk, bk, Wv, bv);
    phase4<<<196, 256>>>();
    phase5<<<P5_TOTAL, 256, p5_smem>>>(out, ei, ew);
    phase6<<<12500, 256>>>(out);
}

// round 9
// speedup vs baseline: 8.7642x; 1.1282x over previous
#include <cuda_runtime.h>
#include <cuda_bf16.h>
#include <math.h>
#include <stdint.h>

#define NN 50000
#define CC 256
#define HH 4
#define DD 64
#define EE 800000
#define OC 256   // H*D
#define FNN 50000.0f

// ---------------- device scratch ----------------
__device__ float g_q[NN * OC];
__device__ float g_vbar[NN * DD];
__device__ float g_S[OC * OC];       // Xs^T Xs
__device__ float g_T[OC * OC];       // Wk @ S
__device__ float g_xsum[OC];
__device__ float g_wvbar[DD * CC];
__device__ float g_bvbar[DD];
__device__ float g_ksum[OC];
__device__ float g_vsum[OC];
__device__ float g_kv[HH * DD * DD]; // [h][d][m]
__device__ float g_scal[2];
__device__ float g_deg[NN];
__device__ int   g_offs[NN + 1];
__device__ int   g_cursor[NN];
__device__ int   g_src[EE];
__device__ float g_val[EE];
__device__ int   g_part[256];
__device__ int   g_sc1done;

// ---------------- helpers ----------------
__device__ __forceinline__ uint32_t f2tf32(float x) {
    uint32_t r;
    asm("cvt.rna.tf32.f32 %0, %1;" : "=r"(r) : "f"(x));
    return r;
}
__device__ __forceinline__ uint32_t pk(float lo, float hi) {
    uint32_t r;
    asm("cvt.rn.bf16x2.f32 %0, %1, %2;" : "=r"(r) : "f"(hi), "f"(lo));
    return r;
}
__device__ __forceinline__ void mma_tf32(float& d0, float& d1, float& d2, float& d3,
                                         const uint32_t* a, const uint32_t* b) {
    asm volatile(
        "mma.sync.aligned.m16n8k8.row.col.f32.tf32.tf32.f32 "
        "{%0,%1,%2,%3}, {%4,%5,%6,%7}, {%8,%9}, {%0,%1,%2,%3};\n"
        : "+f"(d0), "+f"(d1), "+f"(d2), "+f"(d3)
        : "r"(a[0]), "r"(a[1]), "r"(a[2]), "r"(a[3]), "r"(b[0]), "r"(b[1]));
}
__device__ __forceinline__ void mma_bf16(float& d0, float& d1, float& d2, float& d3,
                                         const uint32_t* a, const uint32_t* b) {
    asm volatile(
        "mma.sync.aligned.m16n8k16.row.col.f32.bf16.bf16.f32 "
        "{%0,%1,%2,%3}, {%4,%5,%6,%7}, {%8,%9}, {%0,%1,%2,%3};\n"
        : "+f"(d0), "+f"(d1), "+f"(d2), "+f"(d3)
        : "r"(a[0]), "r"(a[1]), "r"(a[2]), "r"(a[3]), "r"(b[0]), "r"(b[1]));
}

// ---------------- L1: zero scratch + Wvbar prep ----------------
__global__ void zero_kernel(const float* __restrict__ Wv, const float* __restrict__ bv) {
    int i = blockIdx.x * 256 + threadIdx.x;   // 65536
    g_S[i] = 0.f;
    if (i < NN) g_deg[i] = 0.f;
    if (i < OC) g_xsum[i] = 0.f;
    if (i < 2) g_scal[i] = 0.f;
    if (i == 0) g_sc1done = 0;
    if (i < DD * CC) {
        int d = i >> 8, c = i & 255;
        g_wvbar[i] = 0.25f * (Wv[(d) * CC + c] + Wv[(d + 64) * CC + c] +
                              Wv[(d + 128) * CC + c] + Wv[(d + 192) * CC + c]);
    }
    if (i < DD)
        g_bvbar[i] = 0.25f * (bv[i] + bv[i + 64] + bv[i + 128] + bv[i + 192]);
}

// ======================== phase1 bodies ========================
#define BK 32
#define AST 36
#define TSZ (128 * AST)
#define SST 132
#define CHK 1024
#define NCH 49

// ---- SYRK tile body ----
__device__ void syrk_body(float* smf, int bidx, const float* __restrict__ Xs) {
    float* Ai = smf;
    float* Bj = smf + 2 * 32 * SST;
    int t = threadIdx.x;
    int tile = bidx / NCH;            // 0:(0,0) 1:(0,1) 2:(1,1)
    int chunk = bidx % NCH;
    int ci = (tile == 2) ? 1 : 0;
    int cj = (tile == 0) ? 0 : 1;
    int diag = (ci == cj);
    int nbase = chunk * CHK;
    int lane = t & 31, warp = t >> 5;
    int wm = warp & 1, wn = warp >> 1;

    auto load_tile = [&](int stage, int s) {
#pragma unroll
        for (int p = 0; p < 4; p++) {
            int idx = p * 256 + t;
            int r = idx >> 5;
            int c4 = (idx & 31) * 4;
            int node = nbase + s + r;
            int ok = (node < NN);
            const float* srcA = Xs + (size_t)(ok ? node : 0) * CC + ci * 128 + c4;
            uint32_t da = (uint32_t)__cvta_generic_to_shared(&Ai[stage * 32 * SST + r * SST + c4]);
            int sz = ok ? 16 : 0;
            asm volatile("cp.async.cg.shared.global [%0], [%1], 16, %2;\n"
                         :: "r"(da), "l"(srcA), "r"(sz));
            if (!diag) {
                const float* srcB = Xs + (size_t)(ok ? node : 0) * CC + cj * 128 + c4;
                uint32_t db = (uint32_t)__cvta_generic_to_shared(&Bj[stage * 32 * SST + r * SST + c4]);
                asm volatile("cp.async.cg.shared.global [%0], [%1], 16, %2;\n"
                             :: "r"(db), "l"(srcB), "r"(sz));
            }
        }
        asm volatile("cp.async.commit_group;\n");
    };

    float d[4][4][4];
#pragma unroll
    for (int i = 0; i < 4; i++)
#pragma unroll
        for (int j = 0; j < 4; j++)
#pragma unroll
            for (int c = 0; c < 4; c++) d[i][j][c] = 0.f;

    load_tile(0, 0);
    for (int si = 0; si < CHK / 32; si++) {
        if (si < CHK / 32 - 1) {
            load_tile((si + 1) & 1, (si + 1) * 32);
            asm volatile("cp.async.wait_group 1;\n");
        } else {
            asm volatile("cp.async.wait_group 0;\n");
        }
        __syncthreads();
        const float* Af = Ai + (si & 1) * 32 * SST;
        const float* Bf = diag ? Af : (Bj + (si & 1) * 32 * SST);
#pragma unroll
        for (int kf = 0; kf < 2; kf++) {
            int k = kf * 16 + (lane & 3) * 2;
            uint32_t a[4][4], b[4][2];
#pragma unroll
            for (int mf = 0; mf < 4; mf++) {
                int ra = wm * 64 + mf * 16 + (lane >> 2);
                a[mf][0] = pk(Af[k * SST + ra],       Af[(k + 1) * SST + ra]);
                a[mf][1] = pk(Af[k * SST + ra + 8],   Af[(k + 1) * SST + ra + 8]);
                a[mf][2] = pk(Af[(k + 8) * SST + ra], Af[(k + 9) * SST + ra]);
                a[mf][3] = pk(Af[(k + 8) * SST + ra + 8], Af[(k + 9) * SST + ra + 8]);
            }
#pragma unroll
            for (int nf = 0; nf < 4; nf++) {
                int rb = wn * 32 + nf * 8 + (lane >> 2);
                b[nf][0] = pk(Bf[k * SST + rb],       Bf[(k + 1) * SST + rb]);
                b[nf][1] = pk(Bf[(k + 8) * SST + rb], Bf[(k + 9) * SST + rb]);
            }
#pragma unroll
            for (int nf = 0; nf < 4; nf++)
#pragma unroll
                for (int mf = 0; mf < 4; mf++)
                    mma_bf16(d[mf][nf][0], d[mf][nf][1], d[mf][nf][2], d[mf][nf][3],
                             a[mf], b[nf]);
        }
        __syncthreads();
    }
#pragma unroll
    for (int mf = 0; mf < 4; mf++) {
#pragma unroll
        for (int nf = 0; nf < 4; nf++) {
            int row = ci * 128 + wm * 64 + mf * 16 + (lane >> 2);
            int col = cj * 128 + wn * 32 + nf * 8 + (lane & 3) * 2;
            atomicAdd(&g_S[row * 256 + col],       d[mf][nf][0]);
            atomicAdd(&g_S[row * 256 + col + 1],   d[mf][nf][1]);
            atomicAdd(&g_S[(row + 8) * 256 + col], d[mf][nf][2]);
            atomicAdd(&g_S[(row + 8) * 256 + col + 1], d[mf][nf][3]);
        }
    }
}

// ---- Q GEMM body (bf16) ----
__device__ void gemmq_body(float* smf, int bi, const float* __restrict__ X,
                           const float* __restrict__ W, const float* __restrict__ B) {
    float* As = smf;
    float* Bs = smf + 2 * TSZ;
    __shared__ float red8[8];

    int t = threadIdx.x;
    int m0 = (bi >> 1) * 128;
    int n0 = (bi & 1) * 128;
    int lane = t & 31, warp = t >> 5;
    int wm = warp & 1, wn = warp >> 1;
    int lr = t >> 3, lc = (t & 7) * 4;

    auto load_tile = [&](int stage, int k0) {
#pragma unroll
        for (int p = 0; p < 4; p++) {
            int r = p * 32 + lr;
            int gr = m0 + r;
            int ok = (gr < NN);
            const float* srcA = X + (size_t)(ok ? gr : 0) * CC + k0 + lc;
            uint32_t da = (uint32_t)__cvta_generic_to_shared(&As[stage * TSZ + r * AST + lc]);
            int szA = ok ? 16 : 0;
            asm volatile("cp.async.cg.shared.global [%0], [%1], 16, %2;\n"
                         :: "r"(da), "l"(srcA), "r"(szA));
            const float* srcB = W + (size_t)(n0 + r) * CC + k0 + lc;
            uint32_t db = (uint32_t)__cvta_generic_to_shared(&Bs[stage * TSZ + r * AST + lc]);
            asm volatile("cp.async.cg.shared.global [%0], [%1], 16;\n"
                         :: "r"(db), "l"(srcB));
        }
        asm volatile("cp.async.commit_group;\n");
    };

    float d[4][4][4];
#pragma unroll
    for (int i = 0; i < 4; i++)
#pragma unroll
        for (int j = 0; j < 4; j++)
#pragma unroll
            for (int c = 0; c < 4; c++) d[i][j][c] = 0.f;

    load_tile(0, 0);
    for (int ki = 0; ki < CC / BK; ki++) {
        if (ki < CC / BK - 1) {
            load_tile((ki + 1) & 1, (ki + 1) * BK);
            asm volatile("cp.async.wait_group 1;\n");
        } else {
            asm volatile("cp.async.wait_group 0;\n");
        }
        __syncthreads();
        const float* Af = As + (ki & 1) * TSZ;
        const float* Bf = Bs + (ki & 1) * TSZ;
#pragma unroll
        for (int kf = 0; kf < 2; kf++) {
            int ka = kf * 16 + (lane & 3) * 2;
            uint32_t a[4][4], b[4][2];
#pragma unroll
            for (int mf = 0; mf < 4; mf++) {
                int ra = wm * 64 + mf * 16 + (lane >> 2);
                float2 x0 = *(const float2*)&Af[ra * AST + ka];
                float2 x1 = *(const float2*)&Af[(ra + 8) * AST + ka];
                float2 x2 = *(const float2*)&Af[ra * AST + ka + 8];
                float2 x3 = *(const float2*)&Af[(ra + 8) * AST + ka + 8];
                a[mf][0] = pk(x0.x, x0.y); a[mf][1] = pk(x1.x, x1.y);
                a[mf][2] = pk(x2.x, x2.y); a[mf][3] = pk(x3.x, x3.y);
            }
#pragma unroll
            for (int nf = 0; nf < 4; nf++) {
                int rb = wn * 32 + nf * 8 + (lane >> 2);
                float2 y0 = *(const float2*)&Bf[rb * AST + ka];
                float2 y1 = *(const float2*)&Bf[rb * AST + ka + 8];
                b[nf][0] = pk(y0.x, y0.y); b[nf][1] = pk(y1.x, y1.y);
            }
#pragma unroll
            for (int nf = 0; nf < 4; nf++)
#pragma unroll
                for (int mf = 0; mf < 4; mf++)
                    mma_bf16(d[mf][nf][0], d[mf][nf][1], d[mf][nf][2], d[mf][nf][3],
                             a[mf], b[nf]);
        }
        __syncthreads();
    }

    float qs = 0.f;
#pragma unroll
    for (int mf = 0; mf < 4; mf++) {
#pragma unroll
        for (int nf = 0; nf < 4; nf++) {
            int row = m0 + wm * 64 + mf * 16 + (lane >> 2);
            int col = n0 + wn * 32 + nf * 8 + (lane & 3) * 2;
            float bi0 = B[col], bi1 = B[col + 1];
            if (row < NN) {
                float o0 = d[mf][nf][0] + bi0, o1 = d[mf][nf][1] + bi1;
                *(float2*)&g_q[(size_t)row * OC + col] = make_float2(o0, o1);
                qs += o0 * o0 + o1 * o1;
            }
            if (row + 8 < NN) {
                float o0 = d[mf][nf][2] + bi0, o1 = d[mf][nf][3] + bi1;
                *(float2*)&g_q[(size_t)(row + 8) * OC + col] = make_float2(o0, o1);
                qs += o0 * o0 + o1 * o1;
            }
        }
    }
#pragma unroll
    for (int off = 16; off > 0; off >>= 1) qs += __shfl_xor_sync(0xffffffffu, qs, off);
    if (lane == 0) red8[warp] = qs;
    __syncthreads();
    if (t == 0) {
        float s = 0.f;
#pragma unroll
        for (int j = 0; j < 8; j++) s += red8[j];
        atomicAdd(&g_scal[0], s);
    }
}

// ---- vbar GEMM body (tf32) + xsum fold ----
__device__ void vbar_body(float* smf, int bi, const float* __restrict__ Xs) {
    float* As = smf;
    float* Bs = smf + 2 * TSZ;

    int t = threadIdx.x;
    int m0 = bi * 128;
    int lane = t & 31, warp = t >> 5;
    int lr = t >> 3, lc = (t & 7) * 4;

    auto load_tile = [&](int stage, int k0) {
#pragma unroll
        for (int p = 0; p < 4; p++) {
            int r = p * 32 + lr;
            int gr = m0 + r;
            int ok = (gr < NN);
            const float* srcA = Xs + (size_t)(ok ? gr : 0) * CC + k0 + lc;
            uint32_t da = (uint32_t)__cvta_generic_to_shared(&As[stage * TSZ + r * AST + lc]);
            int szA = ok ? 16 : 0;
            asm volatile("cp.async.cg.shared.global [%0], [%1], 16, %2;\n"
                         :: "r"(da), "l"(srcA), "r"(szA));
        }
#pragma unroll
        for (int p = 0; p < 2; p++) {
            int r = p * 32 + lr;
            const float* srcB = g_wvbar + (size_t)r * CC + k0 + lc;
            uint32_t db = (uint32_t)__cvta_generic_to_shared(&Bs[stage * 64 * AST + r * AST + lc]);
            asm volatile("cp.async.cg.shared.global [%0], [%1], 16;\n"
                         :: "r"(db), "l"(srcB));
        }
        asm volatile("cp.async.commit_group;\n");
    };

    float acc[8][4];
#pragma unroll
    for (int i = 0; i < 8; i++)
#pragma unroll
        for (int c = 0; c < 4; c++) acc[i][c] = 0.f;

    load_tile(0, 0);
    for (int ki = 0; ki < CC / BK; ki++) {
        if (ki < CC / BK - 1) {
            load_tile((ki + 1) & 1, (ki + 1) * BK);
            asm volatile("cp.async.wait_group 1;\n");
        } else {
            asm volatile("cp.async.wait_group 0;\n");
        }
        __syncthreads();
        const float* Af = As + (ki & 1) * TSZ;
        const float* Bf = Bs + (ki & 1) * 64 * AST;
        {
            int col = t & 31, rg = t >> 5;
            float p = 0.f;
#pragma unroll
            for (int r = 0; r < 16; r++) p += Af[(rg * 16 + r) * AST + col];
            atomicAdd(&g_xsum[ki * 32 + col], p);
        }
#pragma unroll
        for (int kf = 0; kf < 4; kf++) {
            int ka = kf * 8 + (lane & 3);
            uint32_t a[4];
            int ra = warp * 16 + (lane >> 2);
            a[0] = f2tf32(Af[ra * AST + ka]);
            a[1] = f2tf32(Af[(ra + 8) * AST + ka]);
            a[2] = f2tf32(Af[ra * AST + ka + 4]);
            a[3] = f2tf32(Af[(ra + 8) * AST + ka + 4]);
#pragma unroll
            for (int nf = 0; nf < 8; nf++) {
                int rb = nf * 8 + (lane >> 2);
                uint32_t b[2];
                b[0] = f2tf32(Bf[rb * AST + ka]);
                b[1] = f2tf32(Bf[rb * AST + ka + 4]);
                mma_tf32(acc[nf][0], acc[nf][1], acc[nf][2], acc[nf][3], a, b);
            }
        }
        __syncthreads();
    }
#pragma unroll
    for (int nf = 0; nf < 8; nf++) {
        int row = m0 + warp * 16 + (lane >> 2);
        int col = nf * 8 + (lane & 3) * 2;
        float b0 = g_bvbar[col], b1 = g_bvbar[col + 1];
        if (row < NN)
            *(float2*)&g_vbar[(size_t)row * DD + col] =
                make_float2(acc[nf][0] + b0, acc[nf][1] + b1);
        if (row + 8 < NN)
            *(float2*)&g_vbar[(size_t)(row + 8) * DD + col] =
                make_float2(acc[nf][2] + b0, acc[nf][3] + b1);
    }
}

// ---- phase1 dispatcher: syrk(147) | gemm_q(782) | vbar(391) | degree(391) ----
#define P1_SYRK 147
#define P1_GEMM (P1_SYRK + 782)   // 929
#define P1_VBAR (P1_GEMM + 391)   // 1320
#define P1_TOTAL (P1_VBAR + 391)  // 1711

__global__ void __launch_bounds__(256, 2)
phase1(const float* __restrict__ Xq, const float* __restrict__ Wq, const float* __restrict__ bq,
       const float* __restrict__ Xs, const int* __restrict__ ei)
{
    extern __shared__ float smf[];
    int b = blockIdx.x;
    if (b < P1_SYRK) {
        syrk_body(smf, b, Xs);
    } else if (b < P1_GEMM) {
        gemmq_body(smf, b - P1_SYRK, Xq, Wq, bq);
    } else if (b < P1_VBAR) {
        vbar_body(smf, b - P1_GEMM, Xs);
    } else {
        int gs = b - P1_VBAR;
        for (int e = gs * 256 + threadIdx.x; e < EE; e += 391 * 256)
            atomicAdd(&g_deg[ei[EE + e]], 1.0f);
    }
}

// ======== phase2: fixT(256) | scan1(196) | sumvec(2) | scan2-spin(1) ========
__global__ void phase2(const float* __restrict__ Wk, const float* __restrict__ bk,
                       const float* __restrict__ Wv, const float* __restrict__ bv)
{
    int b = blockIdx.x, t = threadIdx.x;
    if (b < 256) {
        __shared__ float w[256];
        w[t] = Wk[b * CC + t];
        __syncthreads();
        float acc = 0.f;
#pragma unroll 4
        for (int c = 0; c < 256; c++) {
            float s = (c >= 128 && t < 128) ? g_S[t * 256 + c] : g_S[c * 256 + t];
            acc += w[c] * s;
        }
        g_T[b * 256 + t] = acc;
    } else if (b < 452) {
        int blk = b - 256;
        int i = blk * 256 + t;
        int v = (i < NN) ? (int)g_deg[i] : 0;
#pragma unroll
        for (int off = 16; off > 0; off >>= 1) v += __shfl_xor_sync(0xffffffffu, v, off);
        __shared__ int ws[8];
        if ((t & 31) == 0) ws[t >> 5] = v;
        __syncthreads();
        if (t == 0) {
            int s = 0;
#pragma unroll
            for (int j = 0; j < 8; j++) s += ws[j];
            g_part[blk] = s;
            __threadfence();
            atomicAdd(&g_sc1done, 1);
        }
    } else if (b < 454) {
        int sel = b - 452;
        __shared__ float xs[256];
        xs[t] = g_xsum[t];
        __syncthreads();
        const float* W = sel ? Wv : Wk;
        const float* bb = sel ? bv : bk;
        float* dst = sel ? g_vsum : g_ksum;
        float acc = 0.f;
#pragma unroll 4
        for (int c = 0; c < 256; c++) acc += W[t * CC + c] * xs[c];
        dst[t] = acc + FNN * bb[t];
    } else {
        // scan2: spin until all 196 scan1 partials posted, then exclusive-scan them
        if (t == 0) {
            while (atomicAdd(&g_sc1done, 0) < 196) { }
        }
        __syncthreads();
        __threadfence();
        int v = (t < 196) ? g_part[t] : 0;
        int lane = t & 31, w = t >> 5;
        int x = v;
#pragma unroll
        for (int off = 1; off < 32; off <<= 1) {
            int y = __shfl_up_sync(0xffffffffu, x, off);
            if (lane >= off) x += y;
        }
        __shared__ int ws[8];
        if (lane == 31) ws[w] = x;
        __syncthreads();
        if (t == 0) {
            int c = 0;
#pragma unroll
            for (int j = 0; j < 8; j++) { int tmp = ws[j]; ws[j] = c; c += tmp; }
        }
        __syncthreads();
        int incl = x + ws[w];
        if (t < 196) g_part[t] = incl - v;
        if (t == 0) g_offs[NN] = EE;
    }
}

// ======== phase3: kv warp-dot(2048) | ksumsq(64) | scan3(196) ========
#define P3_KV 2048
#define P3_KSQ (P3_KV + 64)      // 2112
#define P3_TOTAL (P3_KSQ + 196)  // 2308

__global__ void phase3(const float* __restrict__ Wk, const float* __restrict__ bk,
                       const float* __restrict__ Wv, const float* __restrict__ bv)
{
    int b = blockIdx.x, t = threadIdx.x;
    if (b < P3_KV) {
        // one warp per kv element, coalesced float4 dot over 256
        int wid = b * 8 + (t >> 5);          // 0..16383
        int lane = t & 31;
        int h = wid >> 12, rem = wid & 4095;
        int dd = rem >> 6, m = rem & 63;
        int rk = h * 64 + m, rv = h * 64 + dd;
        const float4* Tp = (const float4*)&g_T[rk * 256];
        const float4* Wp = (const float4*)&Wv[(size_t)rv * CC];
        float4 t0 = Tp[lane], t1 = Tp[lane + 32];
        float4 w0 = Wp[lane], w1 = Wp[lane + 32];
        float acc = t0.x * w0.x + t0.y * w0.y + t0.z * w0.z + t0.w * w0.w
                  + t1.x * w1.x + t1.y * w1.y + t1.z * w1.z + t1.w * w1.w;
#pragma unroll
        for (int off = 16; off > 0; off >>= 1) acc += __shfl_xor_sync(0xffffffffu, acc, off);
        if (lane == 0) {
            float kx = g_ksum[rk] - FNN * bk[rk];
            float vx = g_vsum[rv] - FNN * bv[rv];
            g_kv[h * 4096 + dd * 64 + m] =
                acc + kx * bv[rv] + bk[rk] * vx + FNN * bk[rk] * bv[rv];
        }
    } else if (b < P3_KSQ) {
        int p = b - P3_KV;
        float acc = 0.f;
#pragma unroll
        for (int j = 0; j < 4; j++) {
            int idx = p * 1024 + j * 256 + t;
            acc += g_T[idx] * Wk[idx];
        }
#pragma unroll
        for (int off = 16; off > 0; off >>= 1) acc += __shfl_xor_sync(0xffffffffu, acc, off);
        __shared__ float r8[8];
        if ((t & 31) == 0) r8[t >> 5] = acc;
        __syncthreads();
        if (t == 0) {
            float s = 0.f;
#pragma unroll
            for (int j = 0; j < 8; j++) s += r8[j];
            if (p == 0) {
                float e = 0.f;
                for (int i = 0; i < 256; i++) {
                    float kx = g_ksum[i] - FNN * bk[i];
                    e += 2.f * bk[i] * kx + FNN * bk[i] * bk[i];
                }
                s += e;
            }
            atomicAdd(&g_scal[1], s);
        }
    } else {
        // scan3
        int blk = b - P3_KSQ;
        int i = blk * 256 + t;
        int v = (i < NN) ? (int)g_deg[i] : 0;
        int lane = t & 31, w = t >> 5;
        int x = v;
#pragma unroll
        for (int off = 1; off < 32; off <<= 1) {
            int y = __shfl_up_sync(0xffffffffu, x, off);
            if (lane >= off) x += y;
        }
        __shared__ int ws[8];
        if (lane == 31) ws[w] = x;
        __syncthreads();
        if (t == 0) {
            int c = 0;
#pragma unroll
            for (int j = 0; j < 8; j++) { int tmp = ws[j]; ws[j] = c; c += tmp; }
        }
        __syncthreads();
        int excl = (x - v) + ws[w] + g_part[blk];
        if (i < NN) { g_offs[i] = excl; g_cursor[i] = excl; }
    }
}

// ======================== phase5: attn(391) | scatter(784 grid-stride) ========================
#define QST 68
#define P5_ATTN 391
#define P5_TOTAL (P5_ATTN + 784)

__device__ void attn_body(uint32_t* sm, int bi, float* __restrict__ out) {
    uint32_t* sq  = sm;
    uint32_t* skv = sm + 128 * QST;
    float* sden = (float*)(skv + 64 * QST);
    float* sks  = sden + 128;
    float* svs  = sks + 64;

    int t = threadIdx.x;
    int lane = t & 31, warp = t >> 5;
    int wm = warp >> 1;
    int wn = warp & 1;
    int m0 = bi * 128;
    float scal = rsqrtf(g_scal[0]) * rsqrtf(g_scal[1]);

    float facc[2][4][4];
#pragma unroll
    for (int i = 0; i < 2; i++)
#pragma unroll
        for (int j = 0; j < 4; j++)
#pragma unroll
            for (int c = 0; c < 4; c++) facc[i][j][c] = 0.f;

    for (int h = 0; h < HH; h++) {
        __syncthreads();
        {
            int r = t >> 4;
            int c = (t & 15) * 4;
#pragma unroll
            for (int p = 0; p < 8; p++) {
                int row = p * 16 + r;
                int n = m0 + row;
                float4 v = make_float4(0.f, 0.f, 0.f, 0.f);
                if (n < NN) v = *(const float4*)&g_q[(size_t)n * OC + h * 64 + c];
                uint4 u = make_uint4(f2tf32(v.x), f2tf32(v.y), f2tf32(v.z), f2tf32(v.w));
                *(uint4*)&sq[row * QST + c] = u;
            }
#pragma unroll
            for (int p = 0; p < 4; p++) {
                int row = p * 16 + r;
                float4 v = *(const float4*)&g_kv[h * 4096 + row * 64 + c];
                uint4 u = make_uint4(f2tf32(v.x), f2tf32(v.y), f2tf32(v.z), f2tf32(v.w));
                *(uint4*)&skv[row * QST + c] = u;
            }
            if (t < 64) { sks[t] = g_ksum[h * 64 + t]; svs[t] = g_vsum[h * 64 + t]; }
        }
        __syncthreads();
        {
            int r = t >> 1, p = t & 1;
            float s = 0.f;
#pragma unroll
            for (int m = 0; m < 32; m++)
                s += __uint_as_float(sq[r * QST + p * 32 + m]) * sks[p * 32 + m];
            s += __shfl_xor_sync(0xffffffffu, s, 1);
            if (p == 0) sden[r] = scal * s + FNN;
        }
        __syncthreads();

        float num[2][4][4];
#pragma unroll
        for (int i = 0; i < 2; i++)
#pragma unroll
            for (int j = 0; j < 4; j++)
#pragma unroll
                for (int c = 0; c < 4; c++) num[i][j][c] = 0.f;

#pragma unroll
        for (int kf = 0; kf < 8; kf++) {
            int ka = kf * 8 + (lane & 3);
            uint32_t a[2][4];
#pragma unroll
            for (int mf = 0; mf < 2; mf++) {
                int ra = wm * 32 + mf * 16 + (lane >> 2);
                a[mf][0] = sq[ra * QST + ka];
                a[mf][1] = sq[(ra + 8) * QST + ka];
                a[mf][2] = sq[ra * QST + ka + 4];
                a[mf][3] = sq[(ra + 8) * QST + ka + 4];
            }
#pragma unroll
            for (int nf = 0; nf < 4; nf++) {
                int rb = wn * 32 + nf * 8 + (lane >> 2);
                uint32_t b[2];
                b[0] = skv[rb * QST + ka];
                b[1] = skv[rb * QST + ka + 4];
#pragma unroll
                for (int mf = 0; mf < 2; mf++)
                    mma_tf32(num[mf][nf][0], num[mf][nf][1], num[mf][nf][2], num[mf][nf][3],
                             a[mf], b);
            }
        }
#pragma unroll
        for (int mf = 0; mf < 2; mf++) {
            int rl = wm * 32 + mf * 16 + (lane >> 2);
            float i0 = 1.f / sden[rl];
            float i1 = 1.f / sden[rl + 8];
#pragma unroll
            for (int nf = 0; nf < 4; nf++) {
                int col = wn * 32 + nf * 8 + (lane & 3) * 2;
                float s0 = svs[col], s1 = svs[col + 1];
                facc[mf][nf][0] += (scal * num[mf][nf][0] + s0) * i0;
                facc[mf][nf][1] += (scal * num[mf][nf][1] + s1) * i0;
                facc[mf][nf][2] += (scal * num[mf][nf][2] + s0) * i1;
                facc[mf][nf][3] += (scal * num[mf][nf][3] + s1) * i1;
            }
        }
    }
#pragma unroll
    for (int mf = 0; mf < 2; mf++) {
#pragma unroll
        for (int nf = 0; nf < 4; nf++) {
            int row = m0 + wm * 32 + mf * 16 + (lane >> 2);
            int col = wn * 32 + nf * 8 + (lane & 3) * 2;
            if (row < NN)
                *(float2*)&out[(size_t)row * 64 + col] =
                    make_float2(0.25f * facc[mf][nf][0], 0.25f * facc[mf][nf][1]);
            if (row + 8 < NN)
                *(float2*)&out[(size_t)(row + 8) * 64 + col] =
                    make_float2(0.25f * facc[mf][nf][2], 0.25f * facc[mf][nf][3]);
        }
    }
}

__global__ void __launch_bounds__(256)
phase5(float* __restrict__ out, const int* __restrict__ ei, const float* __restrict__ ew) {
    extern __shared__ uint32_t smu[];
    int b = blockIdx.x;
    if (b < P5_ATTN) {
        attn_body(smu, b, out);
    } else {
        int gs = b - P5_ATTN;
        for (int e = gs * 256 + threadIdx.x; e < EE; e += 784 * 256) {
            int r = ei[e];
            int c = ei[EE + e];
            float dc = g_deg[c];
            float dr = g_deg[r];
            float w = ew[e];
            float val = (dr > 0.f) ? w * rsqrtf(dc * dr) : 0.f;
            int slot = atomicAdd(&g_cursor[c], 1);
            g_src[slot] = r;
            g_val[slot] = val;
        }
    }
}

// ======================== phase6: GCN gather (atomic-free) ========================
__global__ void phase6(float* __restrict__ out) {
    int t = threadIdx.x;
    int n = blockIdx.x * 4 + (t >> 6);
    int dd = t & 63;
    if (n >= NN) return;
    int e0 = g_offs[n], e1 = g_offs[n + 1];
    float acc = 0.f;
    for (int e = e0; e < e1; ++e) {
        int r = g_src[e];
        float val = g_val[e];
        acc += val * g_vbar[(size_t)r * 64 + dd];
    }
    out[(size_t)n * 64 + dd] += acc;
}

// ---------------- launch ----------------
extern "C" void kernel_launch(void* const* d_in, const int* in_sizes, int n_in,
                              void* d_out, int out_size) {
    const float* query = (const float*)d_in[0];
    const float* source = (const float*)d_in[1];
    const float* Wq = (const float*)d_in[2];
    const float* bq = (const float*)d_in[3];
    const float* Wk = (const float*)d_in[4];
    const float* bk = (const float*)d_in[5];
    const float* Wv = (const float*)d_in[6];
    const float* bv = (const float*)d_in[7];
    const int*   ei = (const int*)d_in[8];
    const float* ew = (const float*)d_in[9];
    float* out = (float*)d_out;

    const int p1_smem = 4 * TSZ * (int)sizeof(float);                       // 73728
    const int p5_smem = (128 * QST + 64 * QST) * 4 + (128 + 64 + 64) * 4;   // 53248

    cudaFuncSetAttribute(phase1, cudaFuncAttributeMaxDynamicSharedMemorySize, p1_smem);
    cudaFuncSetAttribute(phase5, cudaFuncAttributeMaxDynamicSharedMemorySize, p5_smem);

    zero_kernel<<<256, 256>>>(Wv, bv);
    phase1<<<P1_TOTAL, 256, p1_smem>>>(query, Wq, bq, source, ei);
    phase2<<<455, 256>>>(Wk, bk, Wv, bv);
    phase3<<<P3_TOTAL, 256>>>(Wk, bk, Wv, bv);
    phase5<<<P5_TOTAL, 256, p5_smem>>>(out, ei, ew);
    phase6<<<12500, 256>>>(out);
}